// round 4
// baseline (speedup 1.0000x reference)
#include <cuda_runtime.h>
#include <cooperative_groups.h>
#include <math.h>

namespace cg = cooperative_groups;

#define BATCH 256
#define TSTEPS 50
#define INSZ 400
#define G4 1024
#define GAMMA 0.95f
#define EPSF 1e-8f
#define NCTA 128
#define NTHR 512

// ---------- device scratch ----------
__device__ float g_xw[TSTEPS * BATCH * G4];   // x-part of gates, precomputed (52.4MB)
__device__ float g_hA[BATCH * 256];           // h double buffer
__device__ float g_hB[BATCH * 256];
__device__ float g_r[BATCH * 256];            // reads (LSTM input next step)

__device__ __forceinline__ float sigf(float x) { return 1.0f / (1.0f + expf(-x)); }

// ---------- K1: xw[t][b][:] = [x_t, offset_onehot] @ W_ih[0:405] + b_lstm ----------
__global__ __launch_bounds__(256) void k1_xw(
    const float* __restrict__ X, const int* __restrict__ tgt,
    const float* __restrict__ Wih, const float* __restrict__ bl)
{
    __shared__ float As[16][68];
    __shared__ float Bs[16][64];
    const int tid = threadIdx.x;
    const int tx = tid & 15, ty = tid >> 4;
    const int m0 = blockIdx.y * 64, n0 = blockIdx.x * 64;
    const int arow = tid >> 2, akq = tid & 3;
    const int bk = tid >> 4, bc = tid & 15;
    float acc[4][4] = {};
    for (int kt = 0; kt < 25; kt++) {
        float4 av = *(const float4*)(X + (size_t)(m0 + arow) * INSZ + kt * 16 + akq * 4);
        As[akq * 4 + 0][arow] = av.x; As[akq * 4 + 1][arow] = av.y;
        As[akq * 4 + 2][arow] = av.z; As[akq * 4 + 3][arow] = av.w;
        *(float4*)&Bs[bk][bc * 4] =
            *(const float4*)(Wih + (size_t)(kt * 16 + bk) * G4 + n0 + bc * 4);
        __syncthreads();
#pragma unroll
        for (int k = 0; k < 16; k++) {
            float4 a = *(float4*)&As[k][ty * 4];
            float4 b = *(float4*)&Bs[k][tx * 4];
            acc[0][0] += a.x * b.x; acc[0][1] += a.x * b.y; acc[0][2] += a.x * b.z; acc[0][3] += a.x * b.w;
            acc[1][0] += a.y * b.x; acc[1][1] += a.y * b.y; acc[1][2] += a.y * b.z; acc[1][3] += a.y * b.w;
            acc[2][0] += a.z * b.x; acc[2][1] += a.z * b.y; acc[2][2] += a.z * b.z; acc[2][3] += a.z * b.w;
            acc[3][0] += a.w * b.x; acc[3][1] += a.w * b.y; acc[3][2] += a.w * b.z; acc[3][3] += a.w * b.w;
        }
        __syncthreads();
    }
#pragma unroll
    for (int i = 0; i < 4; i++) {
        int m = m0 + ty * 4 + i;
        int bb = m / TSTEPS, t = m % TSTEPS;
        const float* offrow = (t > 0) ? (Wih + (size_t)(400 + tgt[m - 1]) * G4) : (const float*)0;
        float* dst = g_xw + ((size_t)t * BATCH + bb) * G4 + n0 + tx * 4;
#pragma unroll
        for (int j = 0; j < 4; j++) {
            int c = n0 + tx * 4 + j;
            float v = acc[i][j] + bl[c];
            if (offrow) v += offrow[c];
            dst[j] = v;
        }
    }
}

// ---------- fused persistent loop kernel ----------
// smem layout (floats):
#define OFF_M     0        // [2][256*65] = 33280
#define OFF_WR    33280    // [2][1024]
#define OFF_WU    35328    // [2][256]
#define OFF_AS    35840    // [16][33]
#define OFF_BS    36368    // [16][64]  (k, u*4+g)
#define OFF_WK    37392    // [32][260]
#define OFF_K     45712    // [2][256]
#define OFF_SIM   46224    // [2][1024]
#define OFF_WW    48272    // [2][1024] (n*4+r)
#define OFF_H     50320    // [2][256]
#define OFF_RD    50832    // [2][256]
#define OFF_RED   51344    // [2][256]
#define OFF_EX    51856    // [2][16]
#define OFF_WP    51888    // [2][40]
#define OFF_REDI  51968    // int [2][256]
#define OFF_LU    52480    // int [2][4]
#define SMEM_FLOATS 52488
#define SMEM_BYTES (SMEM_FLOATS * 4)

__global__ void __launch_bounds__(NTHR, 1) k_loop(
    const float* __restrict__ Wih, const float* __restrict__ Whh,
    const float* __restrict__ Wkp, const float* __restrict__ bkp,
    const float* __restrict__ Wout, const float* __restrict__ bout,
    float* __restrict__ out)
{
    cg::grid_group grid = cg::this_grid();
    extern __shared__ float sm[];
    float* sM     = sm + OFF_M;
    float* sWr    = sm + OFF_WR;
    float* sWu    = sm + OFF_WU;
    float* As     = sm + OFF_AS;
    float* Bs     = sm + OFF_BS;
    float* sWk    = sm + OFF_WK;
    float* sk     = sm + OFF_K;
    float* ssim   = sm + OFF_SIM;
    float* sww    = sm + OFF_WW;
    float* sh     = sm + OFF_H;
    float* sreads = sm + OFF_RD;
    float* sred   = sm + OFF_RED;
    float* sex    = sm + OFF_EX;
    float* swp    = sm + OFF_WP;
    int*   sredi  = (int*)(sm + OFF_REDI);
    int*   slu    = (int*)(sm + OFF_LU);

    const int tid = threadIdx.x;
    const int cta = blockIdx.x;

    // --- LSTM phase mapping: tile 32 batch x 16 units; thread owns one (b,u) ---
    const int b0L = (cta & 7) * 32;
    const int u0L = (cta >> 3) * 16;
    const int u_l = tid & 15, b_l = tid >> 4;
    const int bL = b0L + b_l, uL = u0L + u_l;

    // --- memory phase mapping: CTA owns batches 2*cta, 2*cta+1 ---
    const int half = tid >> 8, lt = tid & 255;
    const int bM = cta * 2 + half;
    const int lane = tid & 31;
    const int widl = (tid >> 5) & 7;
    const int mOff = half * 16640;   // M base for this half
    const int h256 = half * 256, h1024 = half * 1024, h16 = half * 16;

    // ---------- init state ----------
    for (int e = lt; e < 16384; e += 256) {
        int n = e >> 6, d = e & 63;
        sM[mOff + n * 65 + d] = 1e-6f;
    }
    sWu[h256 + lt] = 1.0f / 256.0f;
#pragma unroll
    for (int rr = 0; rr < 4; rr++) sWr[h1024 + rr * 256 + lt] = 1.0f / 256.0f;
    g_r[bM * 256 + lt] = 0.0f;
    g_hA[bM * 256 + lt] = 0.0f;
    float c_reg = 0.0f;
    grid.sync();

    const float* WihR = Wih + (size_t)405 * G4;

    for (int t = 0; t < TSTEPS; t++) {
        const float* hin  = (t & 1) ? g_hB : g_hA;
        float*       hout = (t & 1) ? g_hA : g_hB;

        // ===== phase 1: LSTM gates GEMM + cell =====
        const float* xwp = g_xw + ((size_t)t * BATCH + bL) * G4;
        float xw0 = xwp[uL], xw1 = xwp[256 + uL], xw2 = xwp[512 + uL], xw3 = xwp[768 + uL];

        float acc0 = 0, acc1 = 0, acc2 = 0, acc3 = 0;
        for (int p = 0; p < 32; p++) {
            const float* src = (p < 16) ? g_r : hin;
            const float* W   = (p < 16) ? WihR : Whh;
            const int kbase = (p & 15) * 16;
            {   // stage A [16k][32b]
                int kk = tid & 15, bb = tid >> 4;
                As[kk * 33 + bb] = src[(b0L + bb) * 256 + kbase + kk];
            }
            {   // stage B [16k][16u][4g]
                int kk = tid >> 5, gp = (tid >> 4) & 1, uu = tid & 15;
                const float* wrow = W + (size_t)(kbase + kk) * G4 + u0L + uu;
                Bs[kk * 64 + uu * 4 + 2 * gp]     = wrow[(2 * gp) * 256];
                Bs[kk * 64 + uu * 4 + 2 * gp + 1] = wrow[(2 * gp + 1) * 256];
            }
            __syncthreads();
#pragma unroll
            for (int k = 0; k < 16; k++) {
                float a = As[k * 33 + b_l];
                float4 bv = *(float4*)&Bs[k * 64 + u_l * 4];
                acc0 += a * bv.x; acc1 += a * bv.y; acc2 += a * bv.z; acc3 += a * bv.w;
            }
            __syncthreads();
        }
        {
            float gi = acc0 + xw0, gf = acc1 + xw1, gg = acc2 + xw2, go = acc3 + xw3;
            c_reg = sigf(gf) * c_reg + sigf(gi) * tanhf(gg);
            hout[bL * 256 + uL] = sigf(go) * tanhf(c_reg);
        }
        grid.sync();

        // ===== phase 2: kp GEMV (smem-staged Wkp) + memory module + head =====
        sh[h256 + lt] = hout[bM * 256 + lt];

        float pc0 = 0.0f, pc1 = 0.0f;
        for (int ch = 0; ch < 8; ch++) {
            __syncthreads();   // sh ready (ch=0) / WAR on sWk (ch>0)
            for (int e = tid; e < 32 * 260; e += NTHR)
                sWk[e] = Wkp[ch * 32 * 260 + e];
            __syncthreads();
#pragma unroll 4
            for (int k = 0; k < 32; k++) {
                float hv = sh[h256 + ch * 32 + k];
                pc0 += hv * sWk[k * 260 + lt];
                if (lt < 4) pc1 += hv * sWk[k * 260 + 256 + lt];
            }
        }
        sk[h256 + lt] = tanhf(pc0 + bkp[lt]);
        if (lt < 4) sex[h16 + 4 + lt] = sigf(pc1 + bkp[256 + lt]);
        __syncthreads();

        // key inverse norms (first 4 warps of each half)
        if (widl < 4) {
            float v0 = sk[h256 + widl * 64 + lane], v1 = sk[h256 + widl * 64 + 32 + lane];
            float s = v0 * v0 + v1 * v1;
#pragma unroll
            for (int o = 16; o > 0; o >>= 1) s += __shfl_xor_sync(0xffffffffu, s, o);
            if (lane == 0) sex[h16 + widl] = 1.0f / (sqrtf(s) + EPSF);
        }

        // top-4 least-used (ascending value, tie -> lower index)
        float myval = sWu[h256 + lt];
        for (int j = 0; j < 4; j++) {
            sred[h256 + lt] = myval; sredi[h256 + lt] = lt;
            __syncthreads();
            for (int s = 128; s > 0; s >>= 1) {
                if (lt < s) {
                    float ov = sred[h256 + lt + s]; int oi = sredi[h256 + lt + s];
                    float cv = sred[h256 + lt];     int ci = sredi[h256 + lt];
                    if (ov < cv || (ov == cv && oi < ci)) { sred[h256 + lt] = ov; sredi[h256 + lt] = oi; }
                }
                __syncthreads();
            }
            if (lt == 0) slu[half * 4 + j] = sredi[h256];
            __syncthreads();
            if (lt == slu[half * 4 + j]) myval = 3.0e38f;
        }

        // write weights w_w[n][r]
        {
            float a0 = sex[h16 + 4], a1 = sex[h16 + 5], a2 = sex[h16 + 6], a3 = sex[h16 + 7];
            const float* wr = sWr + h1024;
            float4 w;
            w.x = a0 * wr[lt]       + (1.0f - a0) * ((lt == slu[half * 4 + 0]) ? 1.0f : 0.0f);
            w.y = a1 * wr[256 + lt] + (1.0f - a1) * ((lt == slu[half * 4 + 1]) ? 1.0f : 0.0f);
            w.z = a2 * wr[512 + lt] + (1.0f - a2) * ((lt == slu[half * 4 + 2]) ? 1.0f : 0.0f);
            w.w = a3 * wr[768 + lt] + (1.0f - a3) * ((lt == slu[half * 4 + 3]) ? 1.0f : 0.0f);
            *(float4*)&sww[h1024 + lt * 4] = w;
        }
        __syncthreads();

        // erase least-used slot + additive write (M stays in smem)
        {
            const int d = lt & 63, nb = lt >> 6;
            const int lu0 = slu[half * 4];
            const float k0 = sk[h256 + d], k1 = sk[h256 + 64 + d],
                        k2 = sk[h256 + 128 + d], k3 = sk[h256 + 192 + d];
            float* mbase = sM + mOff;
#pragma unroll 4
            for (int e = 0; e < 64; e++) {
                int n = e * 4 + nb;
                float4 w = *(float4*)&sww[h1024 + n * 4];
                float v = (n == lu0) ? 0.0f : mbase[n * 65 + d];
                v += w.x * k0 + w.y * k1 + w.z * k2 + w.w * k3;
                mbase[n * 65 + d] = v;
            }
        }
        __syncthreads();

        // row norms + cosine sims (one memory row per thread)
        {
            const float* mrow = sM + mOff + lt * 65;
            const float* kb = sk + h256;
            float s = 0, d0 = 0, d1 = 0, d2 = 0, d3 = 0;
#pragma unroll 8
            for (int dd = 0; dd < 64; dd += 4) {
                float4 kk0 = *(const float4*)&kb[dd];
                float4 kk1 = *(const float4*)&kb[64 + dd];
                float4 kk2 = *(const float4*)&kb[128 + dd];
                float4 kk3 = *(const float4*)&kb[192 + dd];
                float m0 = mrow[dd], m1 = mrow[dd + 1], m2 = mrow[dd + 2], m3 = mrow[dd + 3];
                s  += m0 * m0 + m1 * m1 + m2 * m2 + m3 * m3;
                d0 += m0 * kk0.x + m1 * kk0.y + m2 * kk0.z + m3 * kk0.w;
                d1 += m0 * kk1.x + m1 * kk1.y + m2 * kk1.z + m3 * kk1.w;
                d2 += m0 * kk2.x + m1 * kk2.y + m2 * kk2.z + m3 * kk2.w;
                d3 += m0 * kk3.x + m1 * kk3.y + m2 * kk3.z + m3 * kk3.w;
            }
            float inv = 1.0f / (sqrtf(s) + EPSF);
            ssim[h1024 + lt]       = d0 * inv * sex[h16 + 0];
            ssim[h1024 + 256 + lt] = d1 * inv * sex[h16 + 1];
            ssim[h1024 + 512 + lt] = d2 * inv * sex[h16 + 2];
            ssim[h1024 + 768 + lt] = d3 * inv * sex[h16 + 3];
        }
        __syncthreads();

        // softmax over slots per read head (64-thread groups)
        {
            const int g = lt >> 6, j = lt & 63;
            float* row = ssim + h1024 + g * 256;
            float v0 = row[j], v1 = row[64 + j], v2 = row[128 + j], v3 = row[192 + j];
            float mx = fmaxf(fmaxf(v0, v1), fmaxf(v2, v3));
            sred[h256 + lt] = mx; __syncthreads();
            for (int s = 32; s > 0; s >>= 1) {
                if (j < s) sred[h256 + lt] = fmaxf(sred[h256 + lt], sred[h256 + lt + s]);
                __syncthreads();
            }
            mx = sred[h256 + g * 64]; __syncthreads();
            float e0 = expf(v0 - mx), e1 = expf(v1 - mx), e2 = expf(v2 - mx), e3 = expf(v3 - mx);
            sred[h256 + lt] = e0 + e1 + e2 + e3; __syncthreads();
            for (int s = 32; s > 0; s >>= 1) {
                if (j < s) sred[h256 + lt] += sred[h256 + lt + s];
                __syncthreads();
            }
            float inv = 1.0f / sred[h256 + g * 64];
            row[j] = e0 * inv; row[64 + j] = e1 * inv; row[128 + j] = e2 * inv; row[192 + j] = e3 * inv;
        }
        __syncthreads();

        // usage update + persist w_r (in smem)
        {
            float wrs = ssim[h1024 + lt] + ssim[h1024 + 256 + lt]
                      + ssim[h1024 + 512 + lt] + ssim[h1024 + 768 + lt];
            float4 w = *(float4*)&sww[h1024 + lt * 4];
            sWu[h256 + lt] = GAMMA * sWu[h256 + lt] + wrs + (w.x + w.y + w.z + w.w);
            sWr[h1024 + lt] = ssim[h1024 + lt];
            sWr[h1024 + 256 + lt] = ssim[h1024 + 256 + lt];
            sWr[h1024 + 512 + lt] = ssim[h1024 + 512 + lt];
            sWr[h1024 + 768 + lt] = ssim[h1024 + 768 + lt];
        }
        // reads[r][d]
        {
            const int r = lt >> 6, dd = lt & 63;
            const float* wr2 = ssim + h1024 + r * 256;
            const float* mbase = sM + mOff;
            float a = 0.0f;
#pragma unroll 4
            for (int n = 0; n < 256; n += 4) {
                float4 w = *(const float4*)&wr2[n];
                a += w.x * mbase[n * 65 + dd] + w.y * mbase[(n + 1) * 65 + dd]
                   + w.z * mbase[(n + 2) * 65 + dd] + w.w * mbase[(n + 3) * 65 + dd];
            }
            sreads[h256 + lt] = a;
            g_r[bM * 256 + lt] = a;
        }
        __syncthreads();

        // output head: logits = [h, reads] @ W_out + b_out; softmax
        {
            const float* w1 = Wout + (size_t)lt * 5;
            const float* w2 = Wout + (size_t)(256 + lt) * 5;
            float hv = sh[h256 + lt], rv = sreads[h256 + lt];
            float p0 = hv * w1[0] + rv * w2[0];
            float p1 = hv * w1[1] + rv * w2[1];
            float p2 = hv * w1[2] + rv * w2[2];
            float p3 = hv * w1[3] + rv * w2[3];
            float p4 = hv * w1[4] + rv * w2[4];
#pragma unroll
            for (int o = 16; o > 0; o >>= 1) {
                p0 += __shfl_xor_sync(0xffffffffu, p0, o);
                p1 += __shfl_xor_sync(0xffffffffu, p1, o);
                p2 += __shfl_xor_sync(0xffffffffu, p2, o);
                p3 += __shfl_xor_sync(0xffffffffu, p3, o);
                p4 += __shfl_xor_sync(0xffffffffu, p4, o);
            }
            if (lane == 0) {
                swp[half * 40 + widl * 5 + 0] = p0; swp[half * 40 + widl * 5 + 1] = p1;
                swp[half * 40 + widl * 5 + 2] = p2; swp[half * 40 + widl * 5 + 3] = p3;
                swp[half * 40 + widl * 5 + 4] = p4;
            }
            __syncthreads();
            if (lt == 0) {
                float l[5];
#pragma unroll
                for (int c = 0; c < 5; c++) {
                    float s = bout[c];
#pragma unroll
                    for (int w = 0; w < 8; w++) s += swp[half * 40 + w * 5 + c];
                    l[c] = s;
                }
                float mx = l[0];
#pragma unroll
                for (int c = 1; c < 5; c++) mx = fmaxf(mx, l[c]);
                float e[5], s = 0.0f;
#pragma unroll
                for (int c = 0; c < 5; c++) { e[c] = expf(l[c] - mx); s += e[c]; }
                float inv = 1.0f / s;
                float* o = out + ((size_t)bM * TSTEPS + t) * 5;
#pragma unroll
                for (int c = 0; c < 5; c++) o[c] = e[c] * inv;
            }
        }
        grid.sync();
    }
}

// ---------- launch ----------
extern "C" void kernel_launch(void* const* d_in, const int* in_sizes, int n_in,
                              void* d_out, int out_size) {
    const float* X    = (const float*)d_in[0];
    const int*   tgt  = (const int*)d_in[1];
    const float* Wih  = (const float*)d_in[2];
    const float* Whh  = (const float*)d_in[3];
    const float* bl   = (const float*)d_in[4];
    const float* Wkp  = (const float*)d_in[5];
    const float* bkp  = (const float*)d_in[6];
    const float* Wout = (const float*)d_in[7];
    const float* bout = (const float*)d_in[8];
    float* out = (float*)d_out;

    cudaFuncSetAttribute(k_loop, cudaFuncAttributeMaxDynamicSharedMemorySize, SMEM_BYTES);

    k1_xw<<<dim3(16, 200), 256>>>(X, tgt, Wih, bl);

    void* args[] = { (void*)&Wih, (void*)&Whh, (void*)&Wkp, (void*)&bkp,
                     (void*)&Wout, (void*)&bout, (void*)&out };
    cudaLaunchCooperativeKernel((void*)k_loop, dim3(NCTA), dim3(NTHR), args,
                                SMEM_BYTES, (cudaStream_t)0);
}

// round 5
// speedup vs baseline: 1.1719x; 1.1719x over previous
#include <cuda_runtime.h>
#include <math.h>

#define BATCH 256
#define TSTEPS 50
#define INSZ 400
#define G4 1024
#define GAMMA 0.95f
#define EPSF 1e-8f

// ---------- device scratch ----------
__device__ float g_xw[TSTEPS * BATCH * G4];   // precomputed x@W_ih[0:405] + b  (52.4MB)
__device__ float g_h[BATCH * 256];
__device__ float g_c[BATCH * 256];
__device__ float g_r[BATCH * 256];            // prev reads (flattened [4][64])
__device__ float g_M[BATCH * 256 * 64];       // memory (16.8MB)
__device__ float g_wr[BATCH * 4 * 256];       // read weights
__device__ float g_wu[BATCH * 256];           // usage weights

__device__ __forceinline__ float sigf(float x) { return 1.0f / (1.0f + expf(-x)); }

// ---------- init state ----------
__global__ void k_init() {
    int i = blockIdx.x * blockDim.x + threadIdx.x;
    if (i < BATCH * 256 * 64) g_M[i] = 1e-6f;
    if (i < BATCH * 1024) g_wr[i] = 1.0f / 256.0f;
    if (i < BATCH * 256) {
        g_h[i] = 0.0f; g_c[i] = 0.0f; g_r[i] = 0.0f;
        g_wu[i] = 1.0f / 256.0f;
    }
}

// ---------- K1: xw[t][b][:] = [x_t, offset_onehot] @ W_ih[0:405] + b_lstm ----------
__global__ __launch_bounds__(256) void k1_xw(
    const float* __restrict__ X, const int* __restrict__ tgt,
    const float* __restrict__ Wih, const float* __restrict__ bl)
{
    __shared__ float As[16][68];
    __shared__ float Bs[16][64];
    const int tid = threadIdx.x;
    const int tx = tid & 15, ty = tid >> 4;
    const int m0 = blockIdx.y * 64, n0 = blockIdx.x * 64;
    const int arow = tid >> 2, akq = tid & 3;
    const int bk = tid >> 4, bc = tid & 15;
    float acc[4][4] = {};
    for (int kt = 0; kt < 25; kt++) {
        float4 av = *(const float4*)(X + (size_t)(m0 + arow) * INSZ + kt * 16 + akq * 4);
        As[akq * 4 + 0][arow] = av.x; As[akq * 4 + 1][arow] = av.y;
        As[akq * 4 + 2][arow] = av.z; As[akq * 4 + 3][arow] = av.w;
        *(float4*)&Bs[bk][bc * 4] =
            *(const float4*)(Wih + (size_t)(kt * 16 + bk) * G4 + n0 + bc * 4);
        __syncthreads();
#pragma unroll
        for (int k = 0; k < 16; k++) {
            float4 a = *(float4*)&As[k][ty * 4];
            float4 b = *(float4*)&Bs[k][tx * 4];
            acc[0][0] += a.x * b.x; acc[0][1] += a.x * b.y; acc[0][2] += a.x * b.z; acc[0][3] += a.x * b.w;
            acc[1][0] += a.y * b.x; acc[1][1] += a.y * b.y; acc[1][2] += a.y * b.z; acc[1][3] += a.y * b.w;
            acc[2][0] += a.z * b.x; acc[2][1] += a.z * b.y; acc[2][2] += a.z * b.z; acc[2][3] += a.z * b.w;
            acc[3][0] += a.w * b.x; acc[3][1] += a.w * b.y; acc[3][2] += a.w * b.z; acc[3][3] += a.w * b.w;
        }
        __syncthreads();
    }
#pragma unroll
    for (int i = 0; i < 4; i++) {
        int m = m0 + ty * 4 + i;
        int bb = m / TSTEPS, t = m % TSTEPS;
        const float* offrow = (t > 0) ? (Wih + (size_t)(400 + tgt[m - 1]) * G4) : (const float*)0;
        float* dst = g_xw + ((size_t)t * BATCH + bb) * G4 + n0 + tx * 4;
#pragma unroll
        for (int j = 0; j < 4; j++) {
            int c = n0 + tx * 4 + j;
            float v = acc[i][j] + bl[c];
            if (offrow) v += offrow[c];
            dst[j] = v;
        }
    }
}

// ---------- K2: recurrent GEMM + LSTM fused ----------
__global__ __launch_bounds__(256) void k2_step(
    const float* __restrict__ Wih, const float* __restrict__ Whh, int t)
{
    __shared__ float As[16][34];
    __shared__ float Bs[16][16][4];
    const int tid = threadIdx.x;
    const int tx = tid & 15, ty = tid >> 4;
    const int b0 = blockIdx.x * 32, u0 = blockIdx.y * 16;
    const int arow = tid >> 3, akq = tid & 7;
    const int bk = tid >> 4, bu = tid & 15;

    // prefetch xw epilogue operands early (hide DRAM latency behind GEMM)
    const int uP = u0 + tx;
    const int bP0 = b0 + ty * 2, bP1 = bP0 + 1;
    const float* xwA = g_xw + ((size_t)t * BATCH + bP0) * G4;
    const float* xwB = g_xw + ((size_t)t * BATCH + bP1) * G4;
    float xA0 = xwA[uP], xA1 = xwA[256 + uP], xA2 = xwA[512 + uP], xA3 = xwA[768 + uP];
    float xB0 = xwB[uP], xB1 = xwB[256 + uP], xB2 = xwB[512 + uP], xB3 = xwB[768 + uP];
    float cA = g_c[bP0 * 256 + uP], cB = g_c[bP1 * 256 + uP];

    float acc[2][4] = {};
    for (int kt = 0; kt < 32; kt++) {
        const float* src = (kt < 16) ? g_r : g_h;
        float2 av = *(const float2*)(src + (size_t)(b0 + arow) * 256 + (kt & 15) * 16 + akq * 2);
        As[akq * 2][arow] = av.x; As[akq * 2 + 1][arow] = av.y;
        const float* W = (kt < 16) ? (Wih + (size_t)405 * G4) : Whh;
        int rb = (kt & 15) * 16 + bk;
#pragma unroll
        for (int g = 0; g < 4; g++)
            Bs[bk][bu][g] = W[(size_t)rb * G4 + g * 256 + u0 + bu];
        __syncthreads();
#pragma unroll
        for (int k = 0; k < 16; k++) {
            float a0 = As[k][ty * 2], a1 = As[k][ty * 2 + 1];
            float4 b = *(float4*)&Bs[k][tx][0];
            acc[0][0] += a0 * b.x; acc[0][1] += a0 * b.y; acc[0][2] += a0 * b.z; acc[0][3] += a0 * b.w;
            acc[1][0] += a1 * b.x; acc[1][1] += a1 * b.y; acc[1][2] += a1 * b.z; acc[1][3] += a1 * b.w;
        }
        __syncthreads();
    }
    {
        float gi = acc[0][0] + xA0, gf = acc[0][1] + xA1, gg = acc[0][2] + xA2, go = acc[0][3] + xA3;
        float cc = sigf(gf) * cA + sigf(gi) * tanhf(gg);
        g_c[bP0 * 256 + uP] = cc;
        g_h[bP0 * 256 + uP] = sigf(go) * tanhf(cc);
    }
    {
        float gi = acc[1][0] + xB0, gf = acc[1][1] + xB1, gg = acc[1][2] + xB2, go = acc[1][3] + xB3;
        float cc = sigf(gf) * cB + sigf(gi) * tanhf(gg);
        g_c[bP1 * 256 + uP] = cc;
        g_h[bP1 * 256 + uP] = sigf(go) * tanhf(cc);
    }
}

// ---------- K4: kp GEMV + memory module + output head (one CTA per batch) ----------
__global__ __launch_bounds__(256) void k4_mem(
    const float* __restrict__ Wkp, const float* __restrict__ bkp,
    const float* __restrict__ Wout, const float* __restrict__ bout,
    float* __restrict__ out, int t)
{
    extern __shared__ float sm[];
    float* sM     = sm;              // 256*65 (stride-65 padded)
    float* sk     = sM + 16640;      // 256
    float* ssim   = sk + 256;        // 4*256 (sim -> w_r in place)
    float* sww    = ssim + 1024;     // [n][r] 256*4
    float* swu    = sww + 1024;      // 256
    float* sh     = swu + 256;       // 256
    float* sreads = sh + 256;        // 256
    float* sred   = sreads + 256;    // 256
    float* swp    = sred + 256;      // 40 (warp partials for logits)
    float* sex    = swp + 40;        // 16: [0..3] rk_inv, [4..7] alpha
    int*   sredi  = (int*)(sex + 16);// 256
    int*   slu    = sredi + 256;     // 4

    const int b = blockIdx.x;
    const int tid = threadIdx.x;
    const int lane = tid & 31, wid = tid >> 5;

    // --- loads ---
    swu[tid] = g_wu[b * 256 + tid];
    sh[tid]  = g_h[b * 256 + tid];
    {
        const float4* gm = (const float4*)(g_M + (size_t)b * 16384);
#pragma unroll 4
        for (int e = 0; e < 16; e++) {
            float4 v = gm[e * 256 + tid];
            int gidx = (e * 256 + tid) * 4;
            int n = gidx >> 6, d = gidx & 63;
            float* dst = sM + n * 65 + d;
            dst[0] = v.x; dst[1] = v.y; dst[2] = v.z; dst[3] = v.w;
        }
    }
    __syncthreads();

    // --- kp GEMV: p = h @ W_kp + b_kp (fused, was kernel k3) ---
    {
        float pc = 0.0f;
#pragma unroll 8
        for (int k = 0; k < 256; k++)
            pc += sh[k] * Wkp[(size_t)k * 260 + tid];
        sk[tid] = tanhf(pc + bkp[tid]);
        if (wid < 4) {  // alpha gates: cols 256..259, one per warp
            float a = 0.0f;
#pragma unroll 2
            for (int k = lane; k < 256; k += 32)
                a += sh[k] * Wkp[(size_t)k * 260 + 256 + wid];
#pragma unroll
            for (int o = 16; o > 0; o >>= 1) a += __shfl_xor_sync(0xffffffffu, a, o);
            if (lane == 0) sex[4 + wid] = sigf(a + bkp[256 + wid]);
        }
    }
    __syncthreads();

    // --- key inverse norms (warps 0..3) ---
    if (wid < 4) {
        float v0 = sk[wid * 64 + lane], v1 = sk[wid * 64 + lane + 32];
        float s = v0 * v0 + v1 * v1;
#pragma unroll
        for (int o = 16; o > 0; o >>= 1) s += __shfl_xor_sync(0xffffffffu, s, o);
        if (lane == 0) sex[wid] = 1.0f / (sqrtf(s) + EPSF);
    }

    // --- top-4 least-used (ascending value; tie -> lower index) ---
    float myval = swu[tid];
    for (int j = 0; j < 4; j++) {
        sred[tid] = myval; sredi[tid] = tid;
        __syncthreads();
        for (int s = 128; s > 0; s >>= 1) {
            if (tid < s) {
                float ov = sred[tid + s]; int oi = sredi[tid + s];
                float cv = sred[tid];     int ci = sredi[tid];
                if (ov < cv || (ov == cv && oi < ci)) { sred[tid] = ov; sredi[tid] = oi; }
            }
            __syncthreads();
        }
        if (tid == 0) slu[j] = sredi[0];
        __syncthreads();
        if (tid == slu[j]) myval = 3.0e38f;
    }

    // --- write weights w_w[n][r] ---
    {
        float a0 = sex[4], a1 = sex[5], a2 = sex[6], a3 = sex[7];
        const float* wr = g_wr + (size_t)b * 1024;
        float4 w;
        w.x = a0 * wr[tid]       + (1.0f - a0) * ((tid == slu[0]) ? 1.0f : 0.0f);
        w.y = a1 * wr[256 + tid] + (1.0f - a1) * ((tid == slu[1]) ? 1.0f : 0.0f);
        w.z = a2 * wr[512 + tid] + (1.0f - a2) * ((tid == slu[2]) ? 1.0f : 0.0f);
        w.w = a3 * wr[768 + tid] + (1.0f - a3) * ((tid == slu[3]) ? 1.0f : 0.0f);
        *(float4*)&sww[tid * 4] = w;
    }
    __syncthreads();

    // --- erase slot lu0 + additive write; persist M ---
    {
        const int d = tid & 63, nb = tid >> 6;
        const int lu0 = slu[0];
        const float k0 = sk[d], k1 = sk[64 + d], k2 = sk[128 + d], k3 = sk[192 + d];
        float* gm = g_M + (size_t)b * 16384;
#pragma unroll 4
        for (int e = 0; e < 64; e++) {
            int n = e * 4 + nb;
            int sidx = n * 65 + d;
            float4 w = *(float4*)&sww[n * 4];
            float v = (n == lu0) ? 0.0f : sM[sidx];
            v += w.x * k0 + w.y * k1 + w.z * k2 + w.w * k3;
            sM[sidx] = v;
            gm[n * 64 + d] = v;
        }
    }
    __syncthreads();

    // --- row norms + cosine sims (one memory row per thread) ---
    {
        const float* mrow = sM + tid * 65;
        float s = 0, d0 = 0, d1 = 0, d2 = 0, d3 = 0;
#pragma unroll 8
        for (int dd = 0; dd < 64; dd += 4) {
            float4 kk0 = *(const float4*)&sk[dd];
            float4 kk1 = *(const float4*)&sk[64 + dd];
            float4 kk2 = *(const float4*)&sk[128 + dd];
            float4 kk3 = *(const float4*)&sk[192 + dd];
            float m0 = mrow[dd], m1 = mrow[dd + 1], m2 = mrow[dd + 2], m3 = mrow[dd + 3];
            s  += m0 * m0 + m1 * m1 + m2 * m2 + m3 * m3;
            d0 += m0 * kk0.x + m1 * kk0.y + m2 * kk0.z + m3 * kk0.w;
            d1 += m0 * kk1.x + m1 * kk1.y + m2 * kk1.z + m3 * kk1.w;
            d2 += m0 * kk2.x + m1 * kk2.y + m2 * kk2.z + m3 * kk2.w;
            d3 += m0 * kk3.x + m1 * kk3.y + m2 * kk3.z + m3 * kk3.w;
        }
        float inv = 1.0f / (sqrtf(s) + EPSF);
        ssim[tid]       = d0 * inv * sex[0];
        ssim[256 + tid] = d1 * inv * sex[1];
        ssim[512 + tid] = d2 * inv * sex[2];
        ssim[768 + tid] = d3 * inv * sex[3];
    }
    __syncthreads();

    // --- softmax over slots, per read head (64-thread groups) ---
    {
        const int g = tid >> 6, j = tid & 63;
        float* row = ssim + g * 256;
        float v0 = row[j], v1 = row[64 + j], v2 = row[128 + j], v3 = row[192 + j];
        float mx = fmaxf(fmaxf(v0, v1), fmaxf(v2, v3));
        sred[tid] = mx; __syncthreads();
        for (int s = 32; s > 0; s >>= 1) {
            if (j < s) sred[tid] = fmaxf(sred[tid], sred[tid + s]);
            __syncthreads();
        }
        mx = sred[g * 64]; __syncthreads();
        float e0 = expf(v0 - mx), e1 = expf(v1 - mx), e2 = expf(v2 - mx), e3 = expf(v3 - mx);
        sred[tid] = e0 + e1 + e2 + e3; __syncthreads();
        for (int s = 32; s > 0; s >>= 1) {
            if (j < s) sred[tid] += sred[tid + s];
            __syncthreads();
        }
        float inv = 1.0f / sred[g * 64];
        row[j] = e0 * inv; row[64 + j] = e1 * inv; row[128 + j] = e2 * inv; row[192 + j] = e3 * inv;
    }
    __syncthreads();

    // --- usage update + persist w_r ---
    {
        float wrs = ssim[tid] + ssim[256 + tid] + ssim[512 + tid] + ssim[768 + tid];
        float4 w = *(float4*)&sww[tid * 4];
        g_wu[b * 256 + tid] = GAMMA * swu[tid] + wrs + (w.x + w.y + w.z + w.w);
        float* gwr = g_wr + (size_t)b * 1024;
        gwr[tid] = ssim[tid]; gwr[256 + tid] = ssim[256 + tid];
        gwr[512 + tid] = ssim[512 + tid]; gwr[768 + tid] = ssim[768 + tid];
    }
    // --- reads[r][d] = sum_n w_r[r][n] * M[n][d] ---
    {
        const int r = tid >> 6, dd = tid & 63;
        const float* wr = ssim + r * 256;
        float acc = 0.0f;
#pragma unroll 4
        for (int n = 0; n < 256; n += 4) {
            float4 w = *(const float4*)&wr[n];
            acc += w.x * sM[n * 65 + dd] + w.y * sM[(n + 1) * 65 + dd]
                 + w.z * sM[(n + 2) * 65 + dd] + w.w * sM[(n + 3) * 65 + dd];
        }
        sreads[tid] = acc;
        g_r[b * 256 + tid] = acc;
    }
    __syncthreads();

    // --- logits = [h, reads] @ W_out + b_out; softmax -> out[b][t][:] ---
    {
        const float* w1 = Wout + (size_t)tid * 5;
        const float* w2 = Wout + (size_t)(256 + tid) * 5;
        float hv = sh[tid], rv = sreads[tid];
        float p0 = hv * w1[0] + rv * w2[0];
        float p1 = hv * w1[1] + rv * w2[1];
        float p2 = hv * w1[2] + rv * w2[2];
        float p3 = hv * w1[3] + rv * w2[3];
        float p4 = hv * w1[4] + rv * w2[4];
#pragma unroll
        for (int o = 16; o > 0; o >>= 1) {
            p0 += __shfl_xor_sync(0xffffffffu, p0, o);
            p1 += __shfl_xor_sync(0xffffffffu, p1, o);
            p2 += __shfl_xor_sync(0xffffffffu, p2, o);
            p3 += __shfl_xor_sync(0xffffffffu, p3, o);
            p4 += __shfl_xor_sync(0xffffffffu, p4, o);
        }
        if (lane == 0) {
            swp[wid * 5 + 0] = p0; swp[wid * 5 + 1] = p1; swp[wid * 5 + 2] = p2;
            swp[wid * 5 + 3] = p3; swp[wid * 5 + 4] = p4;
        }
        __syncthreads();
        if (tid == 0) {
            float l[5];
#pragma unroll
            for (int c = 0; c < 5; c++) {
                float s = bout[c];
#pragma unroll
                for (int w = 0; w < 8; w++) s += swp[w * 5 + c];
                l[c] = s;
            }
            float mx = l[0];
#pragma unroll
            for (int c = 1; c < 5; c++) mx = fmaxf(mx, l[c]);
            float e[5], s = 0.0f;
#pragma unroll
            for (int c = 0; c < 5; c++) { e[c] = expf(l[c] - mx); s += e[c]; }
            float inv = 1.0f / s;
            float* o = out + ((size_t)b * TSTEPS + t) * 5;
#pragma unroll
            for (int c = 0; c < 5; c++) o[c] = e[c] * inv;
        }
    }
}

// ---------- launch ----------
extern "C" void kernel_launch(void* const* d_in, const int* in_sizes, int n_in,
                              void* d_out, int out_size) {
    const float* X    = (const float*)d_in[0];
    const int*   tgt  = (const int*)d_in[1];
    const float* Wih  = (const float*)d_in[2];
    const float* Whh  = (const float*)d_in[3];
    const float* bl   = (const float*)d_in[4];
    const float* Wkp  = (const float*)d_in[5];
    const float* bkp  = (const float*)d_in[6];
    const float* Wout = (const float*)d_in[7];
    const float* bout = (const float*)d_in[8];
    float* out = (float*)d_out;

    const int smem4 = (20024 + 260) * 4;   // 81136 B
    cudaFuncSetAttribute(k4_mem, cudaFuncAttributeMaxDynamicSharedMemorySize, smem4);

    k_init<<<16384, 256>>>();
    k1_xw<<<dim3(16, 200), 256>>>(X, tgt, Wih, bl);
    for (int t = 0; t < TSTEPS; t++) {
        k2_step<<<dim3(8, 16), 256>>>(Wih, Whh, t);
        k4_mem<<<256, 256, smem4>>>(Wkp, bkp, Wout, bout, out, t);
    }
}

// round 6
// speedup vs baseline: 1.2001x; 1.0240x over previous
#include <cuda_runtime.h>
#include <math.h>

#define BATCH 256
#define TSTEPS 50
#define INSZ 400
#define G4 1024
#define GAMMA 0.95f
#define EPSF 1e-8f

// ---------- device scratch ----------
__device__ float g_xw[TSTEPS * BATCH * G4];   // precomputed x@W_ih[0:405] + b  (52.4MB)
__device__ float g_h[BATCH * 256];
__device__ float g_c[BATCH * 256];
__device__ float g_r[BATCH * 256];            // prev reads (flattened [4][64])
__device__ float g_M[BATCH * 256 * 64];       // memory (16.8MB)
__device__ float g_wr[BATCH * 4 * 256];       // read weights
__device__ float g_wu[BATCH * 256];           // usage weights

__device__ __forceinline__ float sigf(float x) { return 1.0f / (1.0f + expf(-x)); }

// ---------- init state ----------
__global__ void k_init() {
    int i = blockIdx.x * blockDim.x + threadIdx.x;
    if (i < BATCH * 256 * 64) g_M[i] = 1e-6f;
    if (i < BATCH * 1024) g_wr[i] = 1.0f / 256.0f;
    if (i < BATCH * 256) {
        g_h[i] = 0.0f; g_c[i] = 0.0f; g_r[i] = 0.0f;
        g_wu[i] = 1.0f / 256.0f;
    }
}

// ---------- K1: xw[t][b][:] = [x_t, offset_onehot] @ W_ih[0:405] + b_lstm ----------
__global__ __launch_bounds__(256) void k1_xw(
    const float* __restrict__ X, const int* __restrict__ tgt,
    const float* __restrict__ Wih, const float* __restrict__ bl)
{
    __shared__ float As[16][68];
    __shared__ float Bs[16][64];
    const int tid = threadIdx.x;
    const int tx = tid & 15, ty = tid >> 4;
    const int m0 = blockIdx.y * 64, n0 = blockIdx.x * 64;
    const int arow = tid >> 2, akq = tid & 3;
    const int bk = tid >> 4, bc = tid & 15;
    float acc[4][4] = {};
    for (int kt = 0; kt < 25; kt++) {
        float4 av = *(const float4*)(X + (size_t)(m0 + arow) * INSZ + kt * 16 + akq * 4);
        As[akq * 4 + 0][arow] = av.x; As[akq * 4 + 1][arow] = av.y;
        As[akq * 4 + 2][arow] = av.z; As[akq * 4 + 3][arow] = av.w;
        *(float4*)&Bs[bk][bc * 4] =
            *(const float4*)(Wih + (size_t)(kt * 16 + bk) * G4 + n0 + bc * 4);
        __syncthreads();
#pragma unroll
        for (int k = 0; k < 16; k++) {
            float4 a = *(float4*)&As[k][ty * 4];
            float4 b = *(float4*)&Bs[k][tx * 4];
            acc[0][0] += a.x * b.x; acc[0][1] += a.x * b.y; acc[0][2] += a.x * b.z; acc[0][3] += a.x * b.w;
            acc[1][0] += a.y * b.x; acc[1][1] += a.y * b.y; acc[1][2] += a.y * b.z; acc[1][3] += a.y * b.w;
            acc[2][0] += a.z * b.x; acc[2][1] += a.z * b.y; acc[2][2] += a.z * b.z; acc[2][3] += a.z * b.w;
            acc[3][0] += a.w * b.x; acc[3][1] += a.w * b.y; acc[3][2] += a.w * b.z; acc[3][3] += a.w * b.w;
        }
        __syncthreads();
    }
#pragma unroll
    for (int i = 0; i < 4; i++) {
        int m = m0 + ty * 4 + i;
        int bb = m / TSTEPS, t = m % TSTEPS;
        const float* offrow = (t > 0) ? (Wih + (size_t)(400 + tgt[m - 1]) * G4) : (const float*)0;
        float* dst = g_xw + ((size_t)t * BATCH + bb) * G4 + n0 + tx * 4;
#pragma unroll
        for (int j = 0; j < 4; j++) {
            int c = n0 + tx * 4 + j;
            float v = acc[i][j] + bl[c];
            if (offrow) v += offrow[c];
            dst[j] = v;
        }
    }
}

// ---------- K2: recurrent GEMM + LSTM fused ----------
__global__ __launch_bounds__(256) void k2_step(
    const float* __restrict__ Wih, const float* __restrict__ Whh, int t)
{
    __shared__ float As[16][34];
    __shared__ float Bs[16][16][4];
    const int tid = threadIdx.x;
    const int tx = tid & 15, ty = tid >> 4;
    const int b0 = blockIdx.x * 32, u0 = blockIdx.y * 16;
    const int arow = tid >> 3, akq = tid & 7;
    const int bk = tid >> 4, bu = tid & 15;

    // prefetch xw epilogue operands early (hide DRAM latency behind GEMM)
    const int uP = u0 + tx;
    const int bP0 = b0 + ty * 2, bP1 = bP0 + 1;
    const float* xwA = g_xw + ((size_t)t * BATCH + bP0) * G4;
    const float* xwB = g_xw + ((size_t)t * BATCH + bP1) * G4;
    float xA0 = xwA[uP], xA1 = xwA[256 + uP], xA2 = xwA[512 + uP], xA3 = xwA[768 + uP];
    float xB0 = xwB[uP], xB1 = xwB[256 + uP], xB2 = xwB[512 + uP], xB3 = xwB[768 + uP];
    float cA = g_c[bP0 * 256 + uP], cB = g_c[bP1 * 256 + uP];

    float acc[2][4] = {};
    for (int kt = 0; kt < 32; kt++) {
        const float* src = (kt < 16) ? g_r : g_h;
        float2 av = *(const float2*)(src + (size_t)(b0 + arow) * 256 + (kt & 15) * 16 + akq * 2);
        As[akq * 2][arow] = av.x; As[akq * 2 + 1][arow] = av.y;
        const float* W = (kt < 16) ? (Wih + (size_t)405 * G4) : Whh;
        int rb = (kt & 15) * 16 + bk;
#pragma unroll
        for (int g = 0; g < 4; g++)
            Bs[bk][bu][g] = W[(size_t)rb * G4 + g * 256 + u0 + bu];
        __syncthreads();
#pragma unroll
        for (int k = 0; k < 16; k++) {
            float a0 = As[k][ty * 2], a1 = As[k][ty * 2 + 1];
            float4 b = *(float4*)&Bs[k][tx][0];
            acc[0][0] += a0 * b.x; acc[0][1] += a0 * b.y; acc[0][2] += a0 * b.z; acc[0][3] += a0 * b.w;
            acc[1][0] += a1 * b.x; acc[1][1] += a1 * b.y; acc[1][2] += a1 * b.z; acc[1][3] += a1 * b.w;
        }
        __syncthreads();
    }
    {
        float gi = acc[0][0] + xA0, gf = acc[0][1] + xA1, gg = acc[0][2] + xA2, go = acc[0][3] + xA3;
        float cc = sigf(gf) * cA + sigf(gi) * tanhf(gg);
        g_c[bP0 * 256 + uP] = cc;
        g_h[bP0 * 256 + uP] = sigf(go) * tanhf(cc);
    }
    {
        float gi = acc[1][0] + xB0, gf = acc[1][1] + xB1, gg = acc[1][2] + xB2, go = acc[1][3] + xB3;
        float cc = sigf(gf) * cB + sigf(gi) * tanhf(gg);
        g_c[bP1 * 256 + uP] = cc;
        g_h[bP1 * 256 + uP] = sigf(go) * tanhf(cc);
    }
}

// ---------- K4: kp GEMV (warp-split) + memory module + output head ----------
__global__ __launch_bounds__(256) void k4_mem(
    const float* __restrict__ Wkp, const float* __restrict__ bkp,
    const float* __restrict__ Wout, const float* __restrict__ bout,
    float* __restrict__ out, int t)
{
    extern __shared__ float sm[];
    float* sM     = sm;              // 256*65 (stride-65 padded)
    float* sk     = sM + 16640;      // 256
    float* ssim   = sk + 256;        // 4*256 (sim -> w_r in place)
    float* sww    = ssim + 1024;     // [n][r] 256*4
    float* swu    = sww + 1024;      // 256
    float* sh     = swu + 256;       // 256
    float* sreads = sh + 256;        // 256
    float* sred   = sreads + 256;    // 256
    float* swp    = sred + 256;      // 40 (warp partials for logits)
    float* sex    = swp + 40;        // 16: [0..3] rk_inv, [4..7] alpha
    int*   sredi  = (int*)(sex + 16);// 256
    int*   slu    = sredi + 256;     // 4
    float* spart  = (float*)(slu + 4); // [8][264] kp GEMV partials

    const int b = blockIdx.x;
    const int tid = threadIdx.x;
    const int lane = tid & 31, wid = tid >> 5;

    // --- loads ---
    swu[tid] = g_wu[b * 256 + tid];
    sh[tid]  = g_h[b * 256 + tid];
    {
        const float4* gm = (const float4*)(g_M + (size_t)b * 16384);
#pragma unroll 4
        for (int e = 0; e < 16; e++) {
            float4 v = gm[e * 256 + tid];
            int gidx = (e * 256 + tid) * 4;
            int n = gidx >> 6, d = gidx & 63;
            float* dst = sM + n * 65 + d;
            dst[0] = v.x; dst[1] = v.y; dst[2] = v.z; dst[3] = v.w;
        }
    }
    __syncthreads();

    // --- kp GEMV, warp-split over k: warp w owns k in [32w, 32w+32) ---
    // For each 32-col group: 32 independent coalesced loads (MLP=32/warp).
    {
        const int kbase = wid * 32;
        float hreg[32];
#pragma unroll
        for (int kk = 0; kk < 32; kk++) hreg[kk] = sh[kbase + kk];
#pragma unroll
        for (int g = 0; g < 9; g++) {
            int col = g * 32 + lane;
            if (col < 260) {
                const float* wp = Wkp + (size_t)kbase * 260 + col;
                float part = 0.0f;
#pragma unroll
                for (int kk = 0; kk < 32; kk++)
                    part += hreg[kk] * wp[(size_t)kk * 260];
                spart[wid * 264 + col] = part;
            }
        }
    }
    __syncthreads();
    if (tid < 260) {
        float s = bkp[tid];
#pragma unroll
        for (int w = 0; w < 8; w++) s += spart[w * 264 + tid];
        if (tid < 256) sk[tid] = tanhf(s);
        else sex[4 + (tid - 256)] = sigf(s);
    }
    __syncthreads();

    // --- key inverse norms (warps 0..3) ---
    if (wid < 4) {
        float v0 = sk[wid * 64 + lane], v1 = sk[wid * 64 + lane + 32];
        float s = v0 * v0 + v1 * v1;
#pragma unroll
        for (int o = 16; o > 0; o >>= 1) s += __shfl_xor_sync(0xffffffffu, s, o);
        if (lane == 0) sex[wid] = 1.0f / (sqrtf(s) + EPSF);
    }

    // --- top-4 least-used (ascending value; tie -> lower index) ---
    float myval = swu[tid];
    for (int j = 0; j < 4; j++) {
        sred[tid] = myval; sredi[tid] = tid;
        __syncthreads();
        for (int s = 128; s > 0; s >>= 1) {
            if (tid < s) {
                float ov = sred[tid + s]; int oi = sredi[tid + s];
                float cv = sred[tid];     int ci = sredi[tid];
                if (ov < cv || (ov == cv && oi < ci)) { sred[tid] = ov; sredi[tid] = oi; }
            }
            __syncthreads();
        }
        if (tid == 0) slu[j] = sredi[0];
        __syncthreads();
        if (tid == slu[j]) myval = 3.0e38f;
    }

    // --- write weights w_w[n][r] ---
    {
        float a0 = sex[4], a1 = sex[5], a2 = sex[6], a3 = sex[7];
        const float* wr = g_wr + (size_t)b * 1024;
        float4 w;
        w.x = a0 * wr[tid]       + (1.0f - a0) * ((tid == slu[0]) ? 1.0f : 0.0f);
        w.y = a1 * wr[256 + tid] + (1.0f - a1) * ((tid == slu[1]) ? 1.0f : 0.0f);
        w.z = a2 * wr[512 + tid] + (1.0f - a2) * ((tid == slu[2]) ? 1.0f : 0.0f);
        w.w = a3 * wr[768 + tid] + (1.0f - a3) * ((tid == slu[3]) ? 1.0f : 0.0f);
        *(float4*)&sww[tid * 4] = w;
    }
    __syncthreads();

    // --- erase slot lu0 + additive write; persist M ---
    {
        const int d = tid & 63, nb = tid >> 6;
        const int lu0 = slu[0];
        const float k0 = sk[d], k1 = sk[64 + d], k2 = sk[128 + d], k3 = sk[192 + d];
        float* gm = g_M + (size_t)b * 16384;
#pragma unroll 4
        for (int e = 0; e < 64; e++) {
            int n = e * 4 + nb;
            int sidx = n * 65 + d;
            float4 w = *(float4*)&sww[n * 4];
            float v = (n == lu0) ? 0.0f : sM[sidx];
            v += w.x * k0 + w.y * k1 + w.z * k2 + w.w * k3;
            sM[sidx] = v;
            gm[n * 64 + d] = v;
        }
    }
    __syncthreads();

    // --- row norms + cosine sims (one memory row per thread) ---
    {
        const float* mrow = sM + tid * 65;
        float s = 0, d0 = 0, d1 = 0, d2 = 0, d3 = 0;
#pragma unroll 8
        for (int dd = 0; dd < 64; dd += 4) {
            float4 kk0 = *(const float4*)&sk[dd];
            float4 kk1 = *(const float4*)&sk[64 + dd];
            float4 kk2 = *(const float4*)&sk[128 + dd];
            float4 kk3 = *(const float4*)&sk[192 + dd];
            float m0 = mrow[dd], m1 = mrow[dd + 1], m2 = mrow[dd + 2], m3 = mrow[dd + 3];
            s  += m0 * m0 + m1 * m1 + m2 * m2 + m3 * m3;
            d0 += m0 * kk0.x + m1 * kk0.y + m2 * kk0.z + m3 * kk0.w;
            d1 += m0 * kk1.x + m1 * kk1.y + m2 * kk1.z + m3 * kk1.w;
            d2 += m0 * kk2.x + m1 * kk2.y + m2 * kk2.z + m3 * kk2.w;
            d3 += m0 * kk3.x + m1 * kk3.y + m2 * kk3.z + m3 * kk3.w;
        }
        float inv = 1.0f / (sqrtf(s) + EPSF);
        ssim[tid]       = d0 * inv * sex[0];
        ssim[256 + tid] = d1 * inv * sex[1];
        ssim[512 + tid] = d2 * inv * sex[2];
        ssim[768 + tid] = d3 * inv * sex[3];
    }
    __syncthreads();

    // --- softmax over slots, per read head (64-thread groups) ---
    {
        const int g = tid >> 6, j = tid & 63;
        float* row = ssim + g * 256;
        float v0 = row[j], v1 = row[64 + j], v2 = row[128 + j], v3 = row[192 + j];
        float mx = fmaxf(fmaxf(v0, v1), fmaxf(v2, v3));
        sred[tid] = mx; __syncthreads();
        for (int s = 32; s > 0; s >>= 1) {
            if (j < s) sred[tid] = fmaxf(sred[tid], sred[tid + s]);
            __syncthreads();
        }
        mx = sred[g * 64]; __syncthreads();
        float e0 = expf(v0 - mx), e1 = expf(v1 - mx), e2 = expf(v2 - mx), e3 = expf(v3 - mx);
        sred[tid] = e0 + e1 + e2 + e3; __syncthreads();
        for (int s = 32; s > 0; s >>= 1) {
            if (j < s) sred[tid] += sred[tid + s];
            __syncthreads();
        }
        float inv = 1.0f / sred[g * 64];
        row[j] = e0 * inv; row[64 + j] = e1 * inv; row[128 + j] = e2 * inv; row[192 + j] = e3 * inv;
    }
    __syncthreads();

    // --- usage update + persist w_r ---
    {
        float wrs = ssim[tid] + ssim[256 + tid] + ssim[512 + tid] + ssim[768 + tid];
        float4 w = *(float4*)&sww[tid * 4];
        g_wu[b * 256 + tid] = GAMMA * swu[tid] + wrs + (w.x + w.y + w.z + w.w);
        float* gwr = g_wr + (size_t)b * 1024;
        gwr[tid] = ssim[tid]; gwr[256 + tid] = ssim[256 + tid];
        gwr[512 + tid] = ssim[512 + tid]; gwr[768 + tid] = ssim[768 + tid];
    }
    // --- reads[r][d] = sum_n w_r[r][n] * M[n][d] ---
    {
        const int r = tid >> 6, dd = tid & 63;
        const float* wr = ssim + r * 256;
        float acc = 0.0f;
#pragma unroll 4
        for (int n = 0; n < 256; n += 4) {
            float4 w = *(const float4*)&wr[n];
            acc += w.x * sM[n * 65 + dd] + w.y * sM[(n + 1) * 65 + dd]
                 + w.z * sM[(n + 2) * 65 + dd] + w.w * sM[(n + 3) * 65 + dd];
        }
        sreads[tid] = acc;
        g_r[b * 256 + tid] = acc;
    }
    __syncthreads();

    // --- logits = [h, reads] @ W_out + b_out; softmax -> out[b][t][:] ---
    {
        const float* w1 = Wout + (size_t)tid * 5;
        const float* w2 = Wout + (size_t)(256 + tid) * 5;
        float hv = sh[tid], rv = sreads[tid];
        float p0 = hv * w1[0] + rv * w2[0];
        float p1 = hv * w1[1] + rv * w2[1];
        float p2 = hv * w1[2] + rv * w2[2];
        float p3 = hv * w1[3] + rv * w2[3];
        float p4 = hv * w1[4] + rv * w2[4];
#pragma unroll
        for (int o = 16; o > 0; o >>= 1) {
            p0 += __shfl_xor_sync(0xffffffffu, p0, o);
            p1 += __shfl_xor_sync(0xffffffffu, p1, o);
            p2 += __shfl_xor_sync(0xffffffffu, p2, o);
            p3 += __shfl_xor_sync(0xffffffffu, p3, o);
            p4 += __shfl_xor_sync(0xffffffffu, p4, o);
        }
        if (lane == 0) {
            swp[wid * 5 + 0] = p0; swp[wid * 5 + 1] = p1; swp[wid * 5 + 2] = p2;
            swp[wid * 5 + 3] = p3; swp[wid * 5 + 4] = p4;
        }
        __syncthreads();
        if (tid == 0) {
            float l[5];
#pragma unroll
            for (int c = 0; c < 5; c++) {
                float s = bout[c];
#pragma unroll
                for (int w = 0; w < 8; w++) s += swp[w * 5 + c];
                l[c] = s;
            }
            float mx = l[0];
#pragma unroll
            for (int c = 1; c < 5; c++) mx = fmaxf(mx, l[c]);
            float e[5], s = 0.0f;
#pragma unroll
            for (int c = 0; c < 5; c++) { e[c] = expf(l[c] - mx); s += e[c]; }
            float inv = 1.0f / s;
            float* o = out + ((size_t)b * TSTEPS + t) * 5;
#pragma unroll
            for (int c = 0; c < 5; c++) o[c] = e[c] * inv;
        }
    }
}

// ---------- launch ----------
extern "C" void kernel_launch(void* const* d_in, const int* in_sizes, int n_in,
                              void* d_out, int out_size) {
    const float* X    = (const float*)d_in[0];
    const int*   tgt  = (const int*)d_in[1];
    const float* Wih  = (const float*)d_in[2];
    const float* Whh  = (const float*)d_in[3];
    const float* bl   = (const float*)d_in[4];
    const float* Wkp  = (const float*)d_in[5];
    const float* bkp  = (const float*)d_in[6];
    const float* Wout = (const float*)d_in[7];
    const float* bout = (const float*)d_in[8];
    float* out = (float*)d_out;

    const int smem4 = (20024 + 260 + 8 * 264 + 8) * 4;   // ~89.6KB
    cudaFuncSetAttribute(k4_mem, cudaFuncAttributeMaxDynamicSharedMemorySize, smem4);

    k_init<<<16384, 256>>>();
    k1_xw<<<dim3(16, 200), 256>>>(X, tgt, Wih, bl);
    for (int t = 0; t < TSTEPS; t++) {
        k2_step<<<dim3(8, 16), 256>>>(Wih, Whh, t);
        k4_mem<<<256, 256, smem4>>>(Wkp, bkp, Wout, bout, out, t);
    }
}

// round 7
// speedup vs baseline: 1.3767x; 1.1472x over previous
#include <cuda_runtime.h>
#include <math.h>

#define BATCH 256
#define TSTEPS 50
#define INSZ 400
#define G4 1024
#define GAMMA 0.95f
#define EPSF 1e-8f

// ---------- device scratch ----------
__device__ float g_xw[TSTEPS * BATCH * G4];
__device__ float g_h[BATCH * 256];
__device__ float g_c[BATCH * 256];
__device__ float g_r[BATCH * 256];
__device__ float g_M[BATCH * 256 * 64];
__device__ float g_wr[BATCH * 4 * 256];
__device__ float g_wu[BATCH * 256];

__device__ __forceinline__ float sigf(float x) { return 1.0f / (1.0f + expf(-x)); }

// ---------- init ----------
__global__ void k_init() {
    int i = blockIdx.x * blockDim.x + threadIdx.x;
    if (i < BATCH * 256 * 64) g_M[i] = 1e-6f;
    if (i < BATCH * 1024) g_wr[i] = 1.0f / 256.0f;
    if (i < BATCH * 256) {
        g_h[i] = 0.0f; g_c[i] = 0.0f; g_r[i] = 0.0f;
        g_wu[i] = 1.0f / 256.0f;
    }
}

// ---------- K1: time-parallel input GEMM ----------
__global__ __launch_bounds__(256) void k1_xw(
    const float* __restrict__ X, const int* __restrict__ tgt,
    const float* __restrict__ Wih, const float* __restrict__ bl)
{
    __shared__ float As[16][68];
    __shared__ float Bs[16][64];
    const int tid = threadIdx.x;
    const int tx = tid & 15, ty = tid >> 4;
    const int m0 = blockIdx.y * 64, n0 = blockIdx.x * 64;
    const int arow = tid >> 2, akq = tid & 3;
    const int bk = tid >> 4, bc = tid & 15;
    float acc[4][4] = {};
    for (int kt = 0; kt < 25; kt++) {
        float4 av = *(const float4*)(X + (size_t)(m0 + arow) * INSZ + kt * 16 + akq * 4);
        As[akq * 4 + 0][arow] = av.x; As[akq * 4 + 1][arow] = av.y;
        As[akq * 4 + 2][arow] = av.z; As[akq * 4 + 3][arow] = av.w;
        *(float4*)&Bs[bk][bc * 4] =
            *(const float4*)(Wih + (size_t)(kt * 16 + bk) * G4 + n0 + bc * 4);
        __syncthreads();
#pragma unroll
        for (int k = 0; k < 16; k++) {
            float4 a = *(float4*)&As[k][ty * 4];
            float4 b = *(float4*)&Bs[k][tx * 4];
            acc[0][0] += a.x * b.x; acc[0][1] += a.x * b.y; acc[0][2] += a.x * b.z; acc[0][3] += a.x * b.w;
            acc[1][0] += a.y * b.x; acc[1][1] += a.y * b.y; acc[1][2] += a.y * b.z; acc[1][3] += a.y * b.w;
            acc[2][0] += a.z * b.x; acc[2][1] += a.z * b.y; acc[2][2] += a.z * b.z; acc[2][3] += a.z * b.w;
            acc[3][0] += a.w * b.x; acc[3][1] += a.w * b.y; acc[3][2] += a.w * b.z; acc[3][3] += a.w * b.w;
        }
        __syncthreads();
    }
#pragma unroll
    for (int i = 0; i < 4; i++) {
        int m = m0 + ty * 4 + i;
        int bb = m / TSTEPS, t = m % TSTEPS;
        const float* offrow = (t > 0) ? (Wih + (size_t)(400 + tgt[m - 1]) * G4) : (const float*)0;
        float* dst = g_xw + ((size_t)t * BATCH + bb) * G4 + n0 + tx * 4;
#pragma unroll
        for (int j = 0; j < 4; j++) {
            int c = n0 + tx * 4 + j;
            float v = acc[i][j] + bl[c];
            if (offrow) v += offrow[c];
            dst[j] = v;
        }
    }
}

// ---------- K2: recurrent GEMM + LSTM ----------
__global__ __launch_bounds__(256) void k2_step(
    const float* __restrict__ Wih, const float* __restrict__ Whh, int t)
{
    __shared__ float As[16][34];
    __shared__ float Bs[16][16][4];
    const int tid = threadIdx.x;
    const int tx = tid & 15, ty = tid >> 4;
    const int b0 = blockIdx.x * 32, u0 = blockIdx.y * 16;
    const int arow = tid >> 3, akq = tid & 7;
    const int bk = tid >> 4, bu = tid & 15;

    const int uP = u0 + tx;
    const int bP0 = b0 + ty * 2, bP1 = bP0 + 1;
    const float* xwA = g_xw + ((size_t)t * BATCH + bP0) * G4;
    const float* xwB = g_xw + ((size_t)t * BATCH + bP1) * G4;
    float xA0 = xwA[uP], xA1 = xwA[256 + uP], xA2 = xwA[512 + uP], xA3 = xwA[768 + uP];
    float xB0 = xwB[uP], xB1 = xwB[256 + uP], xB2 = xwB[512 + uP], xB3 = xwB[768 + uP];
    float cA = g_c[bP0 * 256 + uP], cB = g_c[bP1 * 256 + uP];

    float acc[2][4] = {};
    for (int kt = 0; kt < 32; kt++) {
        const float* src = (kt < 16) ? g_r : g_h;
        float2 av = *(const float2*)(src + (size_t)(b0 + arow) * 256 + (kt & 15) * 16 + akq * 2);
        As[akq * 2][arow] = av.x; As[akq * 2 + 1][arow] = av.y;
        const float* W = (kt < 16) ? (Wih + (size_t)405 * G4) : Whh;
        int rb = (kt & 15) * 16 + bk;
#pragma unroll
        for (int g = 0; g < 4; g++)
            Bs[bk][bu][g] = W[(size_t)rb * G4 + g * 256 + u0 + bu];
        __syncthreads();
#pragma unroll
        for (int k = 0; k < 16; k++) {
            float a0 = As[k][ty * 2], a1 = As[k][ty * 2 + 1];
            float4 b = *(float4*)&Bs[k][tx][0];
            acc[0][0] += a0 * b.x; acc[0][1] += a0 * b.y; acc[0][2] += a0 * b.z; acc[0][3] += a0 * b.w;
            acc[1][0] += a1 * b.x; acc[1][1] += a1 * b.y; acc[1][2] += a1 * b.z; acc[1][3] += a1 * b.w;
        }
        __syncthreads();
    }
    {
        float gi = acc[0][0] + xA0, gf = acc[0][1] + xA1, gg = acc[0][2] + xA2, go = acc[0][3] + xA3;
        float cc = sigf(gf) * cA + sigf(gi) * tanhf(gg);
        g_c[bP0 * 256 + uP] = cc;
        g_h[bP0 * 256 + uP] = sigf(go) * tanhf(cc);
    }
    {
        float gi = acc[1][0] + xB0, gf = acc[1][1] + xB1, gg = acc[1][2] + xB2, go = acc[1][3] + xB3;
        float cc = sigf(gf) * cB + sigf(gi) * tanhf(gg);
        g_c[bP1 * 256 + uP] = cc;
        g_h[bP1 * 256 + uP] = sigf(go) * tanhf(cc);
    }
}

// ---------- K4: 512-thread short-critical-path memory module ----------
// smem float offsets
#define O_M     0        // 256*65
#define O_K     16640    // 256
#define O_SIM   16896    // 1024
#define O_WW    17920    // 1024
#define O_WU    18944    // 256
#define O_H     19200    // 256
#define O_RD    19456    // 256
#define O_PR    19712    // 512 (reads partials)
#define O_WP    20224    // 40
#define O_EX    20264    // 16
#define O_SOFT  20280    // 16
#define O_LU    20296    // 4 (int)
#define O_PART  20300    // 16*264 = 4224
#define K4_FLOATS 24524
#define K4_BYTES (K4_FLOATS * 4)

__global__ __launch_bounds__(512) void k4_mem(
    const float* __restrict__ Wkp, const float* __restrict__ bkp,
    const float* __restrict__ Wout, const float* __restrict__ bout,
    float* __restrict__ out, int t)
{
    extern __shared__ float sm[];
    float* sM     = sm + O_M;
    float* sk     = sm + O_K;
    float* ssim   = sm + O_SIM;
    float* sww    = sm + O_WW;
    float* swu    = sm + O_WU;
    float* sh     = sm + O_H;
    float* sreads = sm + O_RD;
    float* spR    = sm + O_PR;
    float* swp    = sm + O_WP;
    float* sex    = sm + O_EX;
    float* ssoft  = sm + O_SOFT;
    int*   slu    = (int*)(sm + O_LU);
    float* spart  = sm + O_PART;

    const int b = blockIdx.x;
    const int tid = threadIdx.x;
    const int lane = tid & 31, wid = tid >> 5;

    // ---- phase 0: loads (M load overlaps with gemv issue window) ----
    if (tid < 256) {
        swu[tid] = g_wu[b * 256 + tid];
        sh[tid]  = g_h[b * 256 + tid];
    }
    {
        const float4* gm4 = (const float4*)(g_M + (size_t)b * 16384);
#pragma unroll
        for (int e = 0; e < 8; e++) {
            float4 v = gm4[e * 512 + tid];
            int gidx = (e * 512 + tid) * 4;
            int n = gidx >> 6, d = gidx & 63;
            float* dst = sM + n * 65 + d;
            dst[0] = v.x; dst[1] = v.y; dst[2] = v.z; dst[3] = v.w;
        }
    }
    __syncthreads();

    // ---- kp GEMV: 16-way k-split, coalesced, high MLP ----
    {
        const int kbase = wid * 16;
        float hreg[16];
#pragma unroll
        for (int kk = 0; kk < 16; kk++) hreg[kk] = sh[kbase + kk];
#pragma unroll
        for (int g = 0; g < 9; g++) {
            int col = g * 32 + lane;
            if (col < 260) {
                const float* wp = Wkp + (size_t)kbase * 260 + col;
                float part = 0.0f;
#pragma unroll
                for (int kk = 0; kk < 16; kk++)
                    part += hreg[kk] * wp[(size_t)kk * 260];
                spart[wid * 264 + col] = part;
            }
        }
    }
    __syncthreads();
    if (tid < 260) {
        float s = bkp[tid];
#pragma unroll
        for (int w = 0; w < 16; w++) s += spart[w * 264 + tid];
        if (tid < 256) sk[tid] = tanhf(s);
        else sex[4 + (tid - 256)] = sigf(s);
    }
    __syncthreads();

    // ---- key norms (warps 0-3) || top-4 least-used (warp 4, barrier-free) ----
    if (wid < 4) {
        float v0 = sk[wid * 64 + lane], v1 = sk[wid * 64 + lane + 32];
        float s = v0 * v0 + v1 * v1;
#pragma unroll
        for (int o = 16; o > 0; o >>= 1) s += __shfl_xor_sync(0xffffffffu, s, o);
        if (lane == 0) sex[wid] = 1.0f / (sqrtf(s) + EPSF);
    } else if (wid == 4) {
        float v[8];
#pragma unroll
        for (int j = 0; j < 8; j++) v[j] = swu[j * 32 + lane];
#pragma unroll
        for (int r = 0; r < 4; r++) {
            float bv = v[0]; int bi = lane;
#pragma unroll
            for (int j = 1; j < 8; j++) {
                int idx = j * 32 + lane;
                if (v[j] < bv) { bv = v[j]; bi = idx; }
            }
#pragma unroll
            for (int o = 16; o > 0; o >>= 1) {
                float ov = __shfl_xor_sync(0xffffffffu, bv, o);
                int   oi = __shfl_xor_sync(0xffffffffu, bi, o);
                if (ov < bv || (ov == bv && oi < bi)) { bv = ov; bi = oi; }
            }
            if (lane == 0) slu[r] = bi;
#pragma unroll
            for (int j = 0; j < 8; j++)
                if (bi == j * 32 + lane) v[j] = 3.0e38f;
        }
    }
    __syncthreads();

    // ---- write weights w_w[n][r] (tid<256) ----
    if (tid < 256) {
        float a0 = sex[4], a1 = sex[5], a2 = sex[6], a3 = sex[7];
        const float* wr = g_wr + (size_t)b * 1024;
        float4 w;
        w.x = a0 * wr[tid]       + (1.0f - a0) * ((tid == slu[0]) ? 1.0f : 0.0f);
        w.y = a1 * wr[256 + tid] + (1.0f - a1) * ((tid == slu[1]) ? 1.0f : 0.0f);
        w.z = a2 * wr[512 + tid] + (1.0f - a2) * ((tid == slu[2]) ? 1.0f : 0.0f);
        w.w = a3 * wr[768 + tid] + (1.0f - a3) * ((tid == slu[3]) ? 1.0f : 0.0f);
        *(float4*)&sww[tid * 4] = w;
    }
    __syncthreads();

    // ---- erase + additive write; persist M (512 threads, 32 iters) ----
    {
        const int d = tid & 63, nb = tid >> 6;      // nb in 0..7
        const int lu0 = slu[0];
        const float k0 = sk[d], k1 = sk[64 + d], k2 = sk[128 + d], k3 = sk[192 + d];
        float* gmw = g_M + (size_t)b * 16384;
#pragma unroll 4
        for (int e = 0; e < 32; e++) {
            int n = e * 8 + nb;
            float4 w = *(float4*)&sww[n * 4];
            float v = (n == lu0) ? 0.0f : sM[n * 65 + d];
            v += w.x * k0 + w.y * k1 + w.z * k2 + w.w * k3;
            sM[n * 65 + d] = v;
            gmw[n * 64 + d] = v;
        }
    }
    __syncthreads();

    // ---- row norms + cosine sims: 2 threads per row ----
    {
        const int row = tid >> 1, hf = tid & 1;
        const float* mrow = sM + row * 65 + hf * 32;
        const float* kb = sk + hf * 32;
        float s = 0, d0 = 0, d1 = 0, d2 = 0, d3 = 0;
#pragma unroll
        for (int dd = 0; dd < 32; dd += 4) {
            float4 kk0 = *(const float4*)&kb[dd];
            float4 kk1 = *(const float4*)&kb[64 + dd];
            float4 kk2 = *(const float4*)&kb[128 + dd];
            float4 kk3 = *(const float4*)&kb[192 + dd];
            float m0 = mrow[dd], m1 = mrow[dd + 1], m2 = mrow[dd + 2], m3 = mrow[dd + 3];
            s  += m0 * m0 + m1 * m1 + m2 * m2 + m3 * m3;
            d0 += m0 * kk0.x + m1 * kk0.y + m2 * kk0.z + m3 * kk0.w;
            d1 += m0 * kk1.x + m1 * kk1.y + m2 * kk1.z + m3 * kk1.w;
            d2 += m0 * kk2.x + m1 * kk2.y + m2 * kk2.z + m3 * kk2.w;
            d3 += m0 * kk3.x + m1 * kk3.y + m2 * kk3.z + m3 * kk3.w;
        }
        s  += __shfl_xor_sync(0xffffffffu, s, 1);
        d0 += __shfl_xor_sync(0xffffffffu, d0, 1);
        d1 += __shfl_xor_sync(0xffffffffu, d1, 1);
        d2 += __shfl_xor_sync(0xffffffffu, d2, 1);
        d3 += __shfl_xor_sync(0xffffffffu, d3, 1);
        if (hf == 0) {
            float inv = 1.0f / (sqrtf(s) + EPSF);
            ssim[row]       = d0 * inv * sex[0];
            ssim[256 + row] = d1 * inv * sex[1];
            ssim[512 + row] = d2 * inv * sex[2];
            ssim[768 + row] = d3 * inv * sex[3];
        }
    }
    __syncthreads();

    // ---- softmax per head (warp-shuffle, 2 barriers) ----
    float e0, e1, e2, e3;
    float* srow = 0;
    int gH = 0;
    if (tid < 256) {
        gH = tid >> 6;
        const int j = tid & 63;
        srow = ssim + gH * 256 + j;
        float v0 = srow[0], v1 = srow[64], v2 = srow[128], v3 = srow[192];
        float mx = fmaxf(fmaxf(v0, v1), fmaxf(v2, v3));
#pragma unroll
        for (int o = 16; o > 0; o >>= 1) mx = fmaxf(mx, __shfl_xor_sync(0xffffffffu, mx, o));
        if (lane == 0) ssoft[gH * 2 + ((tid >> 5) & 1)] = mx;
        e0 = v0; e1 = v1; e2 = v2; e3 = v3;
    }
    __syncthreads();
    if (tid < 256) {
        float mx = fmaxf(ssoft[gH * 2], ssoft[gH * 2 + 1]);
        e0 = expf(e0 - mx); e1 = expf(e1 - mx); e2 = expf(e2 - mx); e3 = expf(e3 - mx);
        float sum = e0 + e1 + e2 + e3;
#pragma unroll
        for (int o = 16; o > 0; o >>= 1) sum += __shfl_xor_sync(0xffffffffu, sum, o);
        if (lane == 0) ssoft[8 + gH * 2 + ((tid >> 5) & 1)] = sum;
    }
    __syncthreads();
    if (tid < 256) {
        float inv = 1.0f / (ssoft[8 + gH * 2] + ssoft[8 + gH * 2 + 1]);
        srow[0] = e0 * inv; srow[64] = e1 * inv; srow[128] = e2 * inv; srow[192] = e3 * inv;
        // usage update + persist w_r
        float wrs = (e0 + e1 + e2 + e3) * inv;
        float4 w = *(float4*)&sww[tid * 4];
        g_wu[b * 256 + tid] = GAMMA * swu[tid] + wrs + (w.x + w.y + w.z + w.w);
    }
    __syncthreads();
    if (tid < 256) {
        float* gwr = g_wr + (size_t)b * 1024;
        gwr[tid] = ssim[tid]; gwr[256 + tid] = ssim[256 + tid];
        gwr[512 + tid] = ssim[512 + tid]; gwr[768 + tid] = ssim[768 + tid];
    }

    // ---- reads[r][d]: 512 threads, split n into halves ----
    {
        const int half = tid >> 8;
        const int r = (tid >> 6) & 3, dd = tid & 63;
        const float* wr2 = ssim + r * 256 + half * 128;
        const float* mbase = sM + half * 128 * 65;
        float acc = 0.0f;
#pragma unroll 4
        for (int n = 0; n < 128; n += 4) {
            float4 w = *(const float4*)&wr2[n];
            acc += w.x * mbase[n * 65 + dd] + w.y * mbase[(n + 1) * 65 + dd]
                 + w.z * mbase[(n + 2) * 65 + dd] + w.w * mbase[(n + 3) * 65 + dd];
        }
        spR[tid] = acc;
    }
    __syncthreads();
    if (tid < 256) {
        float v = spR[tid] + spR[tid + 256];
        sreads[tid] = v;
        g_r[b * 256 + tid] = v;
    }
    __syncthreads();

    // ---- output head ----
    if (tid < 256) {
        const float* w1 = Wout + (size_t)tid * 5;
        const float* w2 = Wout + (size_t)(256 + tid) * 5;
        float hv = sh[tid], rv = sreads[tid];
        float p0 = hv * w1[0] + rv * w2[0];
        float p1 = hv * w1[1] + rv * w2[1];
        float p2 = hv * w1[2] + rv * w2[2];
        float p3 = hv * w1[3] + rv * w2[3];
        float p4 = hv * w1[4] + rv * w2[4];
#pragma unroll
        for (int o = 16; o > 0; o >>= 1) {
            p0 += __shfl_xor_sync(0xffffffffu, p0, o);
            p1 += __shfl_xor_sync(0xffffffffu, p1, o);
            p2 += __shfl_xor_sync(0xffffffffu, p2, o);
            p3 += __shfl_xor_sync(0xffffffffu, p3, o);
            p4 += __shfl_xor_sync(0xffffffffu, p4, o);
        }
        if (lane == 0) {
            swp[wid * 5 + 0] = p0; swp[wid * 5 + 1] = p1; swp[wid * 5 + 2] = p2;
            swp[wid * 5 + 3] = p3; swp[wid * 5 + 4] = p4;
        }
    }
    __syncthreads();
    if (tid == 0) {
        float l[5];
#pragma unroll
        for (int c = 0; c < 5; c++) {
            float s = bout[c];
#pragma unroll
            for (int w = 0; w < 8; w++) s += swp[w * 5 + c];
            l[c] = s;
        }
        float mx = l[0];
#pragma unroll
        for (int c = 1; c < 5; c++) mx = fmaxf(mx, l[c]);
        float e[5], s = 0.0f;
#pragma unroll
        for (int c = 0; c < 5; c++) { e[c] = expf(l[c] - mx); s += e[c]; }
        float inv = 1.0f / s;
        float* o = out + ((size_t)b * TSTEPS + t) * 5;
#pragma unroll
        for (int c = 0; c < 5; c++) o[c] = e[c] * inv;
    }
}

// ---------- launch ----------
extern "C" void kernel_launch(void* const* d_in, const int* in_sizes, int n_in,
                              void* d_out, int out_size) {
    const float* X    = (const float*)d_in[0];
    const int*   tgt  = (const int*)d_in[1];
    const float* Wih  = (const float*)d_in[2];
    const float* Whh  = (const float*)d_in[3];
    const float* bl   = (const float*)d_in[4];
    const float* Wkp  = (const float*)d_in[5];
    const float* bkp  = (const float*)d_in[6];
    const float* Wout = (const float*)d_in[7];
    const float* bout = (const float*)d_in[8];
    float* out = (float*)d_out;

    cudaFuncSetAttribute(k4_mem, cudaFuncAttributeMaxDynamicSharedMemorySize, K4_BYTES);

    k_init<<<16384, 256>>>();
    k1_xw<<<dim3(16, 200), 256>>>(X, tgt, Wih, bl);
    for (int t = 0; t < TSTEPS; t++) {
        k2_step<<<dim3(8, 16), 256>>>(Wih, Whh, t);
        k4_mem<<<256, 512, K4_BYTES>>>(Wkp, bkp, Wout, bout, out, t);
    }
}

// round 8
// speedup vs baseline: 1.4606x; 1.0610x over previous
#include <cuda_runtime.h>
#include <math.h>

#define BATCH 256
#define TSTEPS 50
#define INSZ 400
#define G4 1024
#define GAMMA 0.95f
#define EPSF 1e-8f

// ---------- device scratch ----------
__device__ float g_xw[TSTEPS * BATCH * G4];
__device__ float g_h[BATCH * 256];
__device__ float g_c[BATCH * 256];
__device__ float g_r[BATCH * 256];
__device__ float g_M[BATCH * 256 * 64];
__device__ float g_wr[BATCH * 4 * 256];
__device__ float g_wu[BATCH * 256];

__device__ __forceinline__ float sigf(float x) { return 1.0f / (1.0f + expf(-x)); }

// ---------- init ----------
__global__ void k_init() {
    int i = blockIdx.x * blockDim.x + threadIdx.x;
    if (i < BATCH * 256 * 64) g_M[i] = 1e-6f;
    if (i < BATCH * 1024) g_wr[i] = 1.0f / 256.0f;
    if (i < BATCH * 256) {
        g_h[i] = 0.0f; g_c[i] = 0.0f; g_r[i] = 0.0f;
        g_wu[i] = 1.0f / 256.0f;
    }
}

// ---------- K1: time-parallel input GEMM ----------
__global__ __launch_bounds__(256) void k1_xw(
    const float* __restrict__ X, const int* __restrict__ tgt,
    const float* __restrict__ Wih, const float* __restrict__ bl)
{
    __shared__ float As[16][68];
    __shared__ float Bs[16][64];
    const int tid = threadIdx.x;
    const int tx = tid & 15, ty = tid >> 4;
    const int m0 = blockIdx.y * 64, n0 = blockIdx.x * 64;
    const int arow = tid >> 2, akq = tid & 3;
    const int bk = tid >> 4, bc = tid & 15;
    float acc[4][4] = {};
    for (int kt = 0; kt < 25; kt++) {
        float4 av = *(const float4*)(X + (size_t)(m0 + arow) * INSZ + kt * 16 + akq * 4);
        As[akq * 4 + 0][arow] = av.x; As[akq * 4 + 1][arow] = av.y;
        As[akq * 4 + 2][arow] = av.z; As[akq * 4 + 3][arow] = av.w;
        *(float4*)&Bs[bk][bc * 4] =
            *(const float4*)(Wih + (size_t)(kt * 16 + bk) * G4 + n0 + bc * 4);
        __syncthreads();
#pragma unroll
        for (int k = 0; k < 16; k++) {
            float4 a = *(float4*)&As[k][ty * 4];
            float4 b = *(float4*)&Bs[k][tx * 4];
            acc[0][0] += a.x * b.x; acc[0][1] += a.x * b.y; acc[0][2] += a.x * b.z; acc[0][3] += a.x * b.w;
            acc[1][0] += a.y * b.x; acc[1][1] += a.y * b.y; acc[1][2] += a.y * b.z; acc[1][3] += a.y * b.w;
            acc[2][0] += a.z * b.x; acc[2][1] += a.z * b.y; acc[2][2] += a.z * b.z; acc[2][3] += a.z * b.w;
            acc[3][0] += a.w * b.x; acc[3][1] += a.w * b.y; acc[3][2] += a.w * b.z; acc[3][3] += a.w * b.w;
        }
        __syncthreads();
    }
#pragma unroll
    for (int i = 0; i < 4; i++) {
        int m = m0 + ty * 4 + i;
        int bb = m / TSTEPS, t = m % TSTEPS;
        const float* offrow = (t > 0) ? (Wih + (size_t)(400 + tgt[m - 1]) * G4) : (const float*)0;
        float* dst = g_xw + ((size_t)t * BATCH + bb) * G4 + n0 + tx * 4;
#pragma unroll
        for (int j = 0; j < 4; j++) {
            int c = n0 + tx * 4 + j;
            float v = acc[i][j] + bl[c];
            if (offrow) v += offrow[c];
            dst[j] = v;
        }
    }
}

// ---------- K2: recurrent GEMM + LSTM, double-buffered (1 barrier/iter) ----------
__global__ __launch_bounds__(256) void k2_step(
    const float* __restrict__ Wih, const float* __restrict__ Whh, int t)
{
    __shared__ float As[2][16][33];
    __shared__ float Bs[2][16][68];     // [k][u*4+g], padded
    const int tid = threadIdx.x;
    const int tx = tid & 15, ty = tid >> 4;
    const int b0 = blockIdx.x * 32, u0 = blockIdx.y * 16;
    const int arow = tid >> 3, akq = tid & 7;
    const int bk = tid >> 4, bu = tid & 15;
    const float* WihR = Wih + (size_t)405 * G4;

    // prefetch epilogue operands (hide DRAM latency behind GEMM)
    const int uP = u0 + tx;
    const int bP0 = b0 + ty * 2, bP1 = bP0 + 1;
    const float* xwA = g_xw + ((size_t)t * BATCH + bP0) * G4;
    const float* xwB = g_xw + ((size_t)t * BATCH + bP1) * G4;
    float xA0 = xwA[uP], xA1 = xwA[256 + uP], xA2 = xwA[512 + uP], xA3 = xwA[768 + uP];
    float xB0 = xwB[uP], xB1 = xwB[256 + uP], xB2 = xwB[512 + uP], xB3 = xwB[768 + uP];
    float cA = g_c[bP0 * 256 + uP], cB = g_c[bP1 * 256 + uP];

    // tile 0 -> buffer 0
    {
        float2 av = *(const float2*)(g_r + (size_t)(b0 + arow) * 256 + akq * 2);
        As[0][akq * 2][arow] = av.x; As[0][akq * 2 + 1][arow] = av.y;
        const float* wrow = WihR + (size_t)bk * G4 + u0 + bu;
        Bs[0][bk][bu * 4 + 0] = wrow[0];
        Bs[0][bk][bu * 4 + 1] = wrow[256];
        Bs[0][bk][bu * 4 + 2] = wrow[512];
        Bs[0][bk][bu * 4 + 3] = wrow[768];
    }
    __syncthreads();

    float acc[2][4] = {};
    for (int kt = 0; kt < 32; kt++) {
        const int cur = kt & 1;
        // prefetch next tile into registers (latency hidden by compute below)
        float2 avn = make_float2(0.f, 0.f);
        float bgn0 = 0.f, bgn1 = 0.f, bgn2 = 0.f, bgn3 = 0.f;
        if (kt < 31) {
            const int kn = kt + 1;
            const float* src = (kn < 16) ? g_r : g_h;
            avn = *(const float2*)(src + (size_t)(b0 + arow) * 256 + (kn & 15) * 16 + akq * 2);
            const float* W = (kn < 16) ? WihR : Whh;
            const float* wrow = W + (size_t)((kn & 15) * 16 + bk) * G4 + u0 + bu;
            bgn0 = wrow[0]; bgn1 = wrow[256]; bgn2 = wrow[512]; bgn3 = wrow[768];
        }
#pragma unroll
        for (int k = 0; k < 16; k++) {
            float a0 = As[cur][k][ty * 2], a1 = As[cur][k][ty * 2 + 1];
            float4 b = *(float4*)&Bs[cur][k][tx * 4];
            acc[0][0] += a0 * b.x; acc[0][1] += a0 * b.y; acc[0][2] += a0 * b.z; acc[0][3] += a0 * b.w;
            acc[1][0] += a1 * b.x; acc[1][1] += a1 * b.y; acc[1][2] += a1 * b.z; acc[1][3] += a1 * b.w;
        }
        if (kt < 31) {
            const int nxt = 1 - cur;
            As[nxt][akq * 2][arow] = avn.x; As[nxt][akq * 2 + 1][arow] = avn.y;
            Bs[nxt][bk][bu * 4 + 0] = bgn0;
            Bs[nxt][bk][bu * 4 + 1] = bgn1;
            Bs[nxt][bk][bu * 4 + 2] = bgn2;
            Bs[nxt][bk][bu * 4 + 3] = bgn3;
            __syncthreads();
        }
    }
    {
        float gi = acc[0][0] + xA0, gf = acc[0][1] + xA1, gg = acc[0][2] + xA2, go = acc[0][3] + xA3;
        float cc = sigf(gf) * cA + sigf(gi) * tanhf(gg);
        g_c[bP0 * 256 + uP] = cc;
        g_h[bP0 * 256 + uP] = sigf(go) * tanhf(cc);
    }
    {
        float gi = acc[1][0] + xB0, gf = acc[1][1] + xB1, gg = acc[1][2] + xB2, go = acc[1][3] + xB3;
        float cc = sigf(gf) * cB + sigf(gi) * tanhf(gg);
        g_c[bP1 * 256 + uP] = cc;
        g_h[bP1 * 256 + uP] = sigf(go) * tanhf(cc);
    }
}

// ---------- K4: 512-thread short-critical-path memory module ----------
#define O_M     0        // 256*65
#define O_K     16640    // 256
#define O_SIM   16896    // 1024
#define O_WW    17920    // 1024
#define O_WU    18944    // 256
#define O_H     19200    // 256
#define O_RD    19456    // 256
#define O_PR    19712    // 512
#define O_WP    20224    // 40
#define O_EX    20264    // 16
#define O_SOFT  20280    // 16
#define O_LU    20296    // 4 (int)
#define O_PART  20300    // 16*264
#define K4_FLOATS 24524
#define K4_BYTES (K4_FLOATS * 4)

__global__ __launch_bounds__(512) void k4_mem(
    const float* __restrict__ Wkp, const float* __restrict__ bkp,
    const float* __restrict__ Wout, const float* __restrict__ bout,
    float* __restrict__ out, int t)
{
    extern __shared__ float sm[];
    float* sM     = sm + O_M;
    float* sk     = sm + O_K;
    float* ssim   = sm + O_SIM;
    float* sww    = sm + O_WW;
    float* swu    = sm + O_WU;
    float* sh     = sm + O_H;
    float* sreads = sm + O_RD;
    float* spR    = sm + O_PR;
    float* swp    = sm + O_WP;
    float* sex    = sm + O_EX;
    float* ssoft  = sm + O_SOFT;
    int*   slu    = (int*)(sm + O_LU);
    float* spart  = sm + O_PART;

    const int b = blockIdx.x;
    const int tid = threadIdx.x;
    const int lane = tid & 31, wid = tid >> 5;

    if (tid < 256) {
        swu[tid] = g_wu[b * 256 + tid];
        sh[tid]  = g_h[b * 256 + tid];
    }
    {
        const float4* gm4 = (const float4*)(g_M + (size_t)b * 16384);
#pragma unroll
        for (int e = 0; e < 8; e++) {
            float4 v = gm4[e * 512 + tid];
            int gidx = (e * 512 + tid) * 4;
            int n = gidx >> 6, d = gidx & 63;
            float* dst = sM + n * 65 + d;
            dst[0] = v.x; dst[1] = v.y; dst[2] = v.z; dst[3] = v.w;
        }
    }
    __syncthreads();

    // kp GEMV: 16-way k-split
    {
        const int kbase = wid * 16;
        float hreg[16];
#pragma unroll
        for (int kk = 0; kk < 16; kk++) hreg[kk] = sh[kbase + kk];
#pragma unroll
        for (int g = 0; g < 9; g++) {
            int col = g * 32 + lane;
            if (col < 260) {
                const float* wp = Wkp + (size_t)kbase * 260 + col;
                float part = 0.0f;
#pragma unroll
                for (int kk = 0; kk < 16; kk++)
                    part += hreg[kk] * wp[(size_t)kk * 260];
                spart[wid * 264 + col] = part;
            }
        }
    }
    __syncthreads();
    if (tid < 260) {
        float s = bkp[tid];
#pragma unroll
        for (int w = 0; w < 16; w++) s += spart[w * 264 + tid];
        if (tid < 256) sk[tid] = tanhf(s);
        else sex[4 + (tid - 256)] = sigf(s);
    }
    __syncthreads();

    // key norms (warps 0-3) || top-4 least-used (warp 4)
    if (wid < 4) {
        float v0 = sk[wid * 64 + lane], v1 = sk[wid * 64 + lane + 32];
        float s = v0 * v0 + v1 * v1;
#pragma unroll
        for (int o = 16; o > 0; o >>= 1) s += __shfl_xor_sync(0xffffffffu, s, o);
        if (lane == 0) sex[wid] = 1.0f / (sqrtf(s) + EPSF);
    } else if (wid == 4) {
        float v[8];
#pragma unroll
        for (int j = 0; j < 8; j++) v[j] = swu[j * 32 + lane];
#pragma unroll
        for (int r = 0; r < 4; r++) {
            float bv = v[0]; int bi = lane;
#pragma unroll
            for (int j = 1; j < 8; j++) {
                int idx = j * 32 + lane;
                if (v[j] < bv) { bv = v[j]; bi = idx; }
            }
#pragma unroll
            for (int o = 16; o > 0; o >>= 1) {
                float ov = __shfl_xor_sync(0xffffffffu, bv, o);
                int   oi = __shfl_xor_sync(0xffffffffu, bi, o);
                if (ov < bv || (ov == bv && oi < bi)) { bv = ov; bi = oi; }
            }
            if (lane == 0) slu[r] = bi;
#pragma unroll
            for (int j = 0; j < 8; j++)
                if (bi == j * 32 + lane) v[j] = 3.0e38f;
        }
    }
    __syncthreads();

    if (tid < 256) {
        float a0 = sex[4], a1 = sex[5], a2 = sex[6], a3 = sex[7];
        const float* wr = g_wr + (size_t)b * 1024;
        float4 w;
        w.x = a0 * wr[tid]       + (1.0f - a0) * ((tid == slu[0]) ? 1.0f : 0.0f);
        w.y = a1 * wr[256 + tid] + (1.0f - a1) * ((tid == slu[1]) ? 1.0f : 0.0f);
        w.z = a2 * wr[512 + tid] + (1.0f - a2) * ((tid == slu[2]) ? 1.0f : 0.0f);
        w.w = a3 * wr[768 + tid] + (1.0f - a3) * ((tid == slu[3]) ? 1.0f : 0.0f);
        *(float4*)&sww[tid * 4] = w;
    }
    __syncthreads();

    // erase + additive write; persist M
    {
        const int d = tid & 63, nb = tid >> 6;
        const int lu0 = slu[0];
        const float k0 = sk[d], k1 = sk[64 + d], k2 = sk[128 + d], k3 = sk[192 + d];
        float* gmw = g_M + (size_t)b * 16384;
#pragma unroll 4
        for (int e = 0; e < 32; e++) {
            int n = e * 8 + nb;
            float4 w = *(float4*)&sww[n * 4];
            float v = (n == lu0) ? 0.0f : sM[n * 65 + d];
            v += w.x * k0 + w.y * k1 + w.z * k2 + w.w * k3;
            sM[n * 65 + d] = v;
            gmw[n * 64 + d] = v;
        }
    }
    __syncthreads();

    // row norms + cosine sims: 2 threads per row
    {
        const int row = tid >> 1, hf = tid & 1;
        const float* mrow = sM + row * 65 + hf * 32;
        const float* kb = sk + hf * 32;
        float s = 0, d0 = 0, d1 = 0, d2 = 0, d3 = 0;
#pragma unroll
        for (int dd = 0; dd < 32; dd += 4) {
            float4 kk0 = *(const float4*)&kb[dd];
            float4 kk1 = *(const float4*)&kb[64 + dd];
            float4 kk2 = *(const float4*)&kb[128 + dd];
            float4 kk3 = *(const float4*)&kb[192 + dd];
            float m0 = mrow[dd], m1 = mrow[dd + 1], m2 = mrow[dd + 2], m3 = mrow[dd + 3];
            s  += m0 * m0 + m1 * m1 + m2 * m2 + m3 * m3;
            d0 += m0 * kk0.x + m1 * kk0.y + m2 * kk0.z + m3 * kk0.w;
            d1 += m0 * kk1.x + m1 * kk1.y + m2 * kk1.z + m3 * kk1.w;
            d2 += m0 * kk2.x + m1 * kk2.y + m2 * kk2.z + m3 * kk2.w;
            d3 += m0 * kk3.x + m1 * kk3.y + m2 * kk3.z + m3 * kk3.w;
        }
        s  += __shfl_xor_sync(0xffffffffu, s, 1);
        d0 += __shfl_xor_sync(0xffffffffu, d0, 1);
        d1 += __shfl_xor_sync(0xffffffffu, d1, 1);
        d2 += __shfl_xor_sync(0xffffffffu, d2, 1);
        d3 += __shfl_xor_sync(0xffffffffu, d3, 1);
        if (hf == 0) {
            float inv = 1.0f / (sqrtf(s) + EPSF);
            ssim[row]       = d0 * inv * sex[0];
            ssim[256 + row] = d1 * inv * sex[1];
            ssim[512 + row] = d2 * inv * sex[2];
            ssim[768 + row] = d3 * inv * sex[3];
        }
    }
    __syncthreads();

    // softmax per head (warp-shuffle)
    float e0, e1, e2, e3;
    float* srow = 0;
    int gH = 0;
    if (tid < 256) {
        gH = tid >> 6;
        const int j = tid & 63;
        srow = ssim + gH * 256 + j;
        float v0 = srow[0], v1 = srow[64], v2 = srow[128], v3 = srow[192];
        float mx = fmaxf(fmaxf(v0, v1), fmaxf(v2, v3));
#pragma unroll
        for (int o = 16; o > 0; o >>= 1) mx = fmaxf(mx, __shfl_xor_sync(0xffffffffu, mx, o));
        if (lane == 0) ssoft[gH * 2 + ((tid >> 5) & 1)] = mx;
        e0 = v0; e1 = v1; e2 = v2; e3 = v3;
    }
    __syncthreads();
    if (tid < 256) {
        float mx = fmaxf(ssoft[gH * 2], ssoft[gH * 2 + 1]);
        e0 = expf(e0 - mx); e1 = expf(e1 - mx); e2 = expf(e2 - mx); e3 = expf(e3 - mx);
        float sum = e0 + e1 + e2 + e3;
#pragma unroll
        for (int o = 16; o > 0; o >>= 1) sum += __shfl_xor_sync(0xffffffffu, sum, o);
        if (lane == 0) ssoft[8 + gH * 2 + ((tid >> 5) & 1)] = sum;
    }
    __syncthreads();
    if (tid < 256) {
        float inv = 1.0f / (ssoft[8 + gH * 2] + ssoft[8 + gH * 2 + 1]);
        srow[0] = e0 * inv; srow[64] = e1 * inv; srow[128] = e2 * inv; srow[192] = e3 * inv;
        float wrs = (e0 + e1 + e2 + e3) * inv;
        float4 w = *(float4*)&sww[tid * 4];
        g_wu[b * 256 + tid] = GAMMA * swu[tid] + wrs + (w.x + w.y + w.z + w.w);
    }
    __syncthreads();
    if (tid < 256) {
        float* gwr = g_wr + (size_t)b * 1024;
        gwr[tid] = ssim[tid]; gwr[256 + tid] = ssim[256 + tid];
        gwr[512 + tid] = ssim[512 + tid]; gwr[768 + tid] = ssim[768 + tid];
    }

    // reads[r][d]
    {
        const int half = tid >> 8;
        const int r = (tid >> 6) & 3, dd = tid & 63;
        const float* wr2 = ssim + r * 256 + half * 128;
        const float* mbase = sM + half * 128 * 65;
        float acc = 0.0f;
#pragma unroll 4
        for (int n = 0; n < 128; n += 4) {
            float4 w = *(const float4*)&wr2[n];
            acc += w.x * mbase[n * 65 + dd] + w.y * mbase[(n + 1) * 65 + dd]
                 + w.z * mbase[(n + 2) * 65 + dd] + w.w * mbase[(n + 3) * 65 + dd];
        }
        spR[tid] = acc;
    }
    __syncthreads();
    if (tid < 256) {
        float v = spR[tid] + spR[tid + 256];
        sreads[tid] = v;
        g_r[b * 256 + tid] = v;
    }
    __syncthreads();

    // output head
    if (tid < 256) {
        const float* w1 = Wout + (size_t)tid * 5;
        const float* w2 = Wout + (size_t)(256 + tid) * 5;
        float hv = sh[tid], rv = sreads[tid];
        float p0 = hv * w1[0] + rv * w2[0];
        float p1 = hv * w1[1] + rv * w2[1];
        float p2 = hv * w1[2] + rv * w2[2];
        float p3 = hv * w1[3] + rv * w2[3];
        float p4 = hv * w1[4] + rv * w2[4];
#pragma unroll
        for (int o = 16; o > 0; o >>= 1) {
            p0 += __shfl_xor_sync(0xffffffffu, p0, o);
            p1 += __shfl_xor_sync(0xffffffffu, p1, o);
            p2 += __shfl_xor_sync(0xffffffffu, p2, o);
            p3 += __shfl_xor_sync(0xffffffffu, p3, o);
            p4 += __shfl_xor_sync(0xffffffffu, p4, o);
        }
        if (lane == 0) {
            swp[wid * 5 + 0] = p0; swp[wid * 5 + 1] = p1; swp[wid * 5 + 2] = p2;
            swp[wid * 5 + 3] = p3; swp[wid * 5 + 4] = p4;
        }
    }
    __syncthreads();
    if (tid == 0) {
        float l[5];
#pragma unroll
        for (int c = 0; c < 5; c++) {
            float s = bout[c];
#pragma unroll
            for (int w = 0; w < 8; w++) s += swp[w * 5 + c];
            l[c] = s;
        }
        float mx = l[0];
#pragma unroll
        for (int c = 1; c < 5; c++) mx = fmaxf(mx, l[c]);
        float e[5], s = 0.0f;
#pragma unroll
        for (int c = 0; c < 5; c++) { e[c] = expf(l[c] - mx); s += e[c]; }
        float inv = 1.0f / s;
        float* o = out + ((size_t)b * TSTEPS + t) * 5;
#pragma unroll
        for (int c = 0; c < 5; c++) o[c] = e[c] * inv;
    }
}

// ---------- launch ----------
extern "C" void kernel_launch(void* const* d_in, const int* in_sizes, int n_in,
                              void* d_out, int out_size) {
    const float* X    = (const float*)d_in[0];
    const int*   tgt  = (const int*)d_in[1];
    const float* Wih  = (const float*)d_in[2];
    const float* Whh  = (const float*)d_in[3];
    const float* bl   = (const float*)d_in[4];
    const float* Wkp  = (const float*)d_in[5];
    const float* bkp  = (const float*)d_in[6];
    const float* Wout = (const float*)d_in[7];
    const float* bout = (const float*)d_in[8];
    float* out = (float*)d_out;

    cudaFuncSetAttribute(k4_mem, cudaFuncAttributeMaxDynamicSharedMemorySize, K4_BYTES);

    k_init<<<16384, 256>>>();
    k1_xw<<<dim3(16, 200), 256>>>(X, tgt, Wih, bl);
    for (int t = 0; t < TSTEPS; t++) {
        k2_step<<<dim3(8, 16), 256>>>(Wih, Whh, t);
        k4_mem<<<256, 512, K4_BYTES>>>(Wkp, bkp, Wout, bout, out, t);
    }
}